// round 5
// baseline (speedup 1.0000x reference)
#include <cuda_runtime.h>
#include <cuda_bf16.h>
#include <math.h>
#include <stdint.h>

#define NQ 131072
#define NS 262144
#define D  256
#define C  64
#define MT 128                 // query tile rows per CTA

// ---------------- device scratch ----------------
__device__ float g_psum[C * D];
__device__ int   g_cnt[C];
__device__ uint4 g_Pbf4[2048];   // 32KB: prototypes bf16 [64][256], XOR-swizzled, /p_norm

extern __shared__ char smem_raw[];

__device__ __forceinline__ uint32_t smem_u32(const void* p) {
    uint32_t a;
    asm("{ .reg .u64 t; cvta.to.shared.u64 t, %1; cvt.u32.u64 %0, t; }" : "=r"(a) : "l"(p));
    return a;
}

// ---------------- zero ----------------
__global__ void k_zero() {
    int i = blockIdx.x * blockDim.x + threadIdx.x;
    if (i < C * D) g_psum[i] = 0.0f;
    if (i < C)     g_cnt[i]  = 0;
}

// ---------------- segment sum v3 ----------------
// 512 blocks: bit0 = dim-half h; block covers 1024 rows of its 128-dim half.
// 256 thr = 4 groups x 64; group g has a PRIVATE 32KB accumulator [64][128];
// thread owns dims {h*128 + 2*tg, +1} exclusively -> no atomics, no aliasing.
// Chain per thread = 256 RMWs; loads double-buffered 8 rows deep.
#define SEG_ROWS 1024
#define SEG_RPG  256

#define SEG_PF(vv, ll, base) do {                                              \
    _Pragma("unroll")                                                          \
    for (int j = 0; j < 8; j++) {                                              \
        ll[j] = __ldg(Lp + (base) + j);                                        \
        vv[j] = __ldg((const float2*)(Sp + (rowbase + (base) + j) * D));       \
    } } while (0)

#define SEG_RMW(vv, ll) do {                                                   \
    _Pragma("unroll")                                                          \
    for (int j = 0; j < 8; j++) {                                              \
        float2* a = (float2*)(my + ll[j] * 128 + tg * 2);                      \
        float2 t = *a;                                                         \
        t.x += vv[j].x; t.y += vv[j].y;                                        \
        *a = t;                                                                \
    } } while (0)

__global__ void __launch_bounds__(256, 1) k_seg(const float* __restrict__ S,
                                                const int* __restrict__ L) {
    float* acc = (float*)smem_raw;                 // 4 copies x 8192 floats (128KB)
    int*   cnt = (int*)(smem_raw + 131072);
    const int tid = threadIdx.x;
    const int g   = tid >> 6;
    const int tg  = tid & 63;
    const int h   = blockIdx.x & 1;
    const size_t rowbase = (size_t)(blockIdx.x >> 1) * SEG_ROWS + (size_t)g * SEG_RPG;
    float* my = acc + g * 8192;

    for (int i = tid; i < 32768; i += 256) acc[i] = 0.0f;
    if (tid < C) cnt[tid] = 0;
    __syncthreads();

    const float* Sp = S + h * 128 + tg * 2;
    const int*   Lp = L + rowbase;

    float2 v0[8], v1[8]; int l0[8], l1[8];
    SEG_PF(v0, l0, 0);
    for (int i = 0; i < SEG_RPG; i += 16) {
        SEG_PF(v1, l1, i + 8);
        SEG_RMW(v0, l0);
        if (i + 16 < SEG_RPG) SEG_PF(v0, l0, i + 16);
        SEG_RMW(v1, l1);
    }
    __syncthreads();

    // merge 4 copies -> global
    for (int e = tid; e < 8192; e += 256) {
        float s = acc[e] + acc[e + 8192] + acc[e + 16384] + acc[e + 24576];
        int c = e >> 7, d = e & 127;
        atomicAdd(&g_psum[c * D + h * 128 + d], s);
    }
    // counts: h==0 blocks only (uniform branch)
    if (h == 0) {
        const int* Lc = L + (size_t)(blockIdx.x >> 1) * SEG_ROWS;
        int4 v = __ldg((const int4*)(Lc + tid * 4));
        atomicAdd(&cnt[v.x], 1); atomicAdd(&cnt[v.y], 1);
        atomicAdd(&cnt[v.z], 1); atomicAdd(&cnt[v.w], 1);
        __syncthreads();
        if (tid < C) atomicAdd(&g_cnt[tid], cnt[tid]);
    }
}

// ---------------- finalize: normalized bf16 prototypes, pre-swizzled ----------------
__global__ void k_fin() {
    __shared__ float red[64];
    int c = blockIdx.x, t = threadIdx.x;
    float denom = fmaxf((float)g_cnt[c], 1.0f);
    float4 p = *(float4*)&g_psum[c * D + t * 4];
    float inv_d = 1.0f / denom;
    p.x *= inv_d; p.y *= inv_d; p.z *= inv_d; p.w *= inv_d;
    red[t] = p.x * p.x + p.y * p.y + p.z * p.z + p.w * p.w;
    __syncthreads();
    for (int s = 32; s > 0; s >>= 1) {
        if (t < s) red[t] += red[t + s];
        __syncthreads();
    }
    float inv = 1.0f / fmaxf(sqrtf(red[0]), 1e-8f);
    float pv[4] = { p.x * inv, p.y * inv, p.z * inv, p.w * inv };
    __nv_bfloat16* dst = (__nv_bfloat16*)g_Pbf4;
#pragma unroll
    for (int j = 0; j < 4; j++) {
        int k = t * 4 + j;
        uint32_t byte = (uint32_t)(c * 512 + ((((k >> 3) ^ (c & 7))) << 4) + (k & 7) * 2);
        dst[byte >> 1] = __float2bfloat16_rn(pv[j]);
    }
}

// fast exp on the FMA pipe
__device__ __forceinline__ float fexp(float x) {
    float y = x * 1.442695041f;
    float r = y + 12582912.0f;
    int n = __float_as_int(r) - 0x4B400000;
    float f = y - (r - 12582912.0f);
    float p = 1.3333558e-3f;
    p = fmaf(p, f, 9.6181291e-3f);
    p = fmaf(p, f, 5.5504109e-2f);
    p = fmaf(p, f, 2.4022651e-1f);
    p = fmaf(p, f, 6.9314718e-1f);
    p = fmaf(p, f, 1.0f);
    return __int_as_float(__float_as_int(p) + (n << 23));
}

__device__ __forceinline__ void ldm4(uint32_t& r0, uint32_t& r1, uint32_t& r2, uint32_t& r3,
                                     uint32_t addr) {
    asm volatile("ldmatrix.sync.aligned.m8n8.x4.shared.b16 {%0,%1,%2,%3}, [%4];"
                 : "=r"(r0), "=r"(r1), "=r"(r2), "=r"(r3) : "r"(addr));
}
__device__ __forceinline__ void mma16816(float* d, uint32_t a0, uint32_t a1, uint32_t a2,
                                         uint32_t a3, uint32_t b0, uint32_t b1) {
    asm volatile("mma.sync.aligned.m16n8k16.row.col.f32.bf16.bf16.f32 "
                 "{%0,%1,%2,%3}, {%4,%5,%6,%7}, {%8,%9}, {%0,%1,%2,%3};"
                 : "+f"(d[0]), "+f"(d[1]), "+f"(d[2]), "+f"(d[3])
                 : "r"(a0), "r"(a1), "r"(a2), "r"(a3), "r"(b0), "r"(b1));
}

// ---------------- query kernel: HMMA bf16 GEMM + fused log_softmax ----------------
// 1024 CTAs x 256 thr; tile 128 q x 64 c x K=256; K split into 2 halves so
// half-1 LDGs overlap ksteps 0..7.
// smem: qss[128] @0, B(32KB) @512, A(64KB) @33280
#define OFF_QSS  0
#define OFF_B    512
#define OFF_A    33280
#define SMEM_QRY (OFF_A + MT * 512)

__global__ void __launch_bounds__(256, 2) k_query(const float* __restrict__ Q,
                                                  float* __restrict__ out) {
    uint32_t sb = smem_u32(smem_raw);
    float* qss = (float*)(smem_raw + OFF_QSS);
    const int tid = threadIdx.x;
    const int wid = tid >> 5;
    const int lid = tid & 31;
    const int qbase = blockIdx.x * MT;

    if (tid < MT) qss[tid] = 0.0f;

    // stage B: 32KB pre-swizzled copy
#pragma unroll
    for (int it = 0; it < 8; it++)
        ((uint4*)(smem_raw + OFF_B))[tid + it * 256] = __ldg(&g_Pbf4[tid + it * 256]);

    __syncthreads();   // qss zeroed, B visible

    // per-half staging: it 0..15, row = it*8 + wid, col4 = lid + 32*half
    auto stage_half = [&](int half) {
#pragma unroll
        for (int it = 0; it < 16; it++) {
            int row  = it * 8 + wid;
            int col4 = lid + 32 * half;
            float4 v = __ldg(((const float4*)Q) + (size_t)(qbase + row) * (D / 4) + col4);
            __nv_bfloat162 p0 = __floats2bfloat162_rn(v.x, v.y);
            __nv_bfloat162 p1 = __floats2bfloat162_rn(v.z, v.w);
            uint2 u = { *(uint32_t*)&p0, *(uint32_t*)&p1 };
            uint32_t addr = OFF_A + row * 512 + ((((col4 >> 1) ^ (row & 7))) << 4) + ((col4 & 1) << 3);
            *(uint2*)(smem_raw + addr) = u;
            float s = v.x * v.x + v.y * v.y + v.z * v.z + v.w * v.w;
#pragma unroll
            for (int w = 16; w > 0; w >>= 1) s += __shfl_xor_sync(0xffffffffu, s, w);
            if (lid == 0) atomicAdd(&qss[row], s);
        }
    };

    float dacc[8][4];
#pragma unroll
    for (int nt = 0; nt < 8; nt++)
#pragma unroll
        for (int j = 0; j < 4; j++) dacc[nt][j] = 0.0f;

    const int am    = lid >> 3;
    const int arow  = wid * 16 + (am & 1) * 8 + (lid & 7);
    const int agsel = am >> 1;
    const int brow0 = (am >> 1) * 8 + (lid & 7);
    const int bgsel = am & 1;

    auto do_kstep = [&](int s) {
        uint32_t a0, a1, a2, a3;
        uint32_t ga = 2 * s + agsel;
        ldm4(a0, a1, a2, a3, sb + OFF_A + arow * 512 + (((ga ^ (arow & 7))) << 4));
        uint32_t bfr[16];
#pragma unroll
        for (int pp = 0; pp < 4; pp++) {
            int row = pp * 16 + brow0;
            uint32_t gb = 2 * s + bgsel;
            ldm4(bfr[pp * 4], bfr[pp * 4 + 1], bfr[pp * 4 + 2], bfr[pp * 4 + 3],
                 sb + OFF_B + row * 512 + (((gb ^ (row & 7))) << 4));
        }
#pragma unroll
        for (int nt = 0; nt < 8; nt++)
            mma16816(dacc[nt], a0, a1, a2, a3, bfr[nt * 2], bfr[nt * 2 + 1]);
    };

    stage_half(0);
    __syncthreads();

    // half-1 LDGs issue here and fly under ksteps 0..7 (disjoint smem regions)
    stage_half(1);
#pragma unroll
    for (int s = 0; s < 8; s++) do_kstep(s);
    __syncthreads();
#pragma unroll
    for (int s = 8; s < 16; s++) do_kstep(s);

    // ---- epilogue: per-row log_softmax within 4-lane quad ----
    float dA[16], dB[16];
#pragma unroll
    for (int nt = 0; nt < 8; nt++) {
        dA[nt * 2] = dacc[nt][0]; dA[nt * 2 + 1] = dacc[nt][1];
        dB[nt * 2] = dacc[nt][2]; dB[nt * 2 + 1] = dacc[nt][3];
    }
    const int rA = wid * 16 + (lid >> 2);
    const int rB = rA + 8;
    float invA = 1.0f / fmaxf(sqrtf(qss[rA]), 1e-8f);
    float invB = 1.0f / fmaxf(sqrtf(qss[rB]), 1e-8f);

    float mA = -3.4e38f, mB = -3.4e38f;
#pragma unroll
    for (int j = 0; j < 16; j++) {
        dA[j] *= invA; mA = fmaxf(mA, dA[j]);
        dB[j] *= invB; mB = fmaxf(mB, dB[j]);
    }
#pragma unroll
    for (int w = 1; w < 4; w <<= 1) {
        mA = fmaxf(mA, __shfl_xor_sync(0xffffffffu, mA, w));
        mB = fmaxf(mB, __shfl_xor_sync(0xffffffffu, mB, w));
    }
    float sA = 0.0f, sB = 0.0f;
#pragma unroll
    for (int j = 0; j < 16; j++) {
        sA += fexp(dA[j] - mA);
        sB += fexp(dB[j] - mB);
    }
#pragma unroll
    for (int w = 1; w < 4; w <<= 1) {
        sA += __shfl_xor_sync(0xffffffffu, sA, w);
        sB += __shfl_xor_sync(0xffffffffu, sB, w);
    }
    float lseA = mA + logf(sA);
    float lseB = mB + logf(sB);

    float* oA = out + (size_t)(qbase + rA) * C + (lid & 3) * 2;
    float* oB = out + (size_t)(qbase + rB) * C + (lid & 3) * 2;
#pragma unroll
    for (int nt = 0; nt < 8; nt++) {
        float2 a = { dA[nt * 2] - lseA, dA[nt * 2 + 1] - lseA };
        float2 b = { dB[nt * 2] - lseB, dB[nt * 2 + 1] - lseB };
        __stcs((float2*)(oA + nt * 8), a);
        __stcs((float2*)(oB + nt * 8), b);
    }
}

extern "C" void kernel_launch(void* const* d_in, const int* in_sizes, int n_in,
                              void* d_out, int out_size) {
    const float* support = (const float*)d_in[0];
    const int*   labels  = (const int*)d_in[1];
    const float* query   = (const float*)d_in[2];
    float*       out     = (float*)d_out;

    const int seg_smem = 131072 + 256;
    cudaFuncSetAttribute(k_seg,   cudaFuncAttributeMaxDynamicSharedMemorySize, seg_smem);
    cudaFuncSetAttribute(k_query, cudaFuncAttributeMaxDynamicSharedMemorySize, SMEM_QRY);

    k_zero<<<(C * D + 255) / 256, 256>>>();
    k_seg<<<512, 256, seg_smem>>>(support, labels);
    k_fin<<<C, 64>>>();
    k_query<<<NQ / MT, 256, SMEM_QRY>>>(query, out);
}

// round 6
// speedup vs baseline: 1.4273x; 1.4273x over previous
#include <cuda_runtime.h>
#include <cuda_bf16.h>
#include <math.h>
#include <stdint.h>

#define NQ 131072
#define NS 262144
#define D  256
#define C  64
#define MT 128

// ---------------- device scratch ----------------
__device__ int   g_cnt[C];
__device__ uint4 g_Pbf4[2048];              // 32KB: prototypes bf16, swizzled, /p_norm
__device__ float g_part[1024 * 8192];       // 32MB: per-CTA partial [64][128]

extern __shared__ char smem_raw[];

__device__ __forceinline__ uint32_t smem_u32(const void* p) {
    uint32_t a;
    asm("{ .reg .u64 t; cvta.to.shared.u64 t, %1; cvt.u32.u64 %0, t; }" : "=r"(a) : "l"(p));
    return a;
}
__device__ __forceinline__ void ldm4(uint32_t& r0, uint32_t& r1, uint32_t& r2, uint32_t& r3,
                                     uint32_t addr) {
    asm volatile("ldmatrix.sync.aligned.m8n8.x4.shared.b16 {%0,%1,%2,%3}, [%4];"
                 : "=r"(r0), "=r"(r1), "=r"(r2), "=r"(r3) : "r"(addr));
}
__device__ __forceinline__ void ldm4t(uint32_t& r0, uint32_t& r1, uint32_t& r2, uint32_t& r3,
                                      uint32_t addr) {
    asm volatile("ldmatrix.sync.aligned.m8n8.x4.trans.shared.b16 {%0,%1,%2,%3}, [%4];"
                 : "=r"(r0), "=r"(r1), "=r"(r2), "=r"(r3) : "r"(addr));
}
__device__ __forceinline__ void mma16816(float* d, uint32_t a0, uint32_t a1, uint32_t a2,
                                         uint32_t a3, uint32_t b0, uint32_t b1) {
    asm volatile("mma.sync.aligned.m16n8k16.row.col.f32.bf16.bf16.f32 "
                 "{%0,%1,%2,%3}, {%4,%5,%6,%7}, {%8,%9}, {%0,%1,%2,%3};"
                 : "+f"(d[0]), "+f"(d[1]), "+f"(d[2]), "+f"(d[3])
                 : "r"(a0), "r"(a1), "r"(a2), "r"(a3), "r"(b0), "r"(b1));
}

// ---------------- zero counts ----------------
__global__ void k_zero() {
    int i = blockIdx.x * blockDim.x + threadIdx.x;
    if (i < C) g_cnt[i] = 0;
}

// ---------------- segment sum as GEMM: partial[c][d] = OneHot^T @ S ----------------
// 1024 CTAs: kc = b>>1 (512 rows), h = b&1 (dim half). 256 thr, 8 warps x 16 dims.
// smem: buf[2] 64rows x 128dims bf16 (16KB ea), labels[2][64], cnt[64]
#define KCHUNK 512
#define TROWS  64
#define SEG_SMEM (32768 + 512 + 256)

__global__ void __launch_bounds__(256, 2) k_seg(const float* __restrict__ S,
                                                const int* __restrict__ L) {
    uint32_t sb = smem_u32(smem_raw);
    int* labs = (int*)(smem_raw + 32768);       // [2][64]
    int* cnts = (int*)(smem_raw + 33280);
    const int tid = threadIdx.x;
    const int wid = tid >> 5;
    const int lid = tid & 31;
    const int kc  = blockIdx.x >> 1;
    const int h   = blockIdx.x & 1;
    const size_t rowbase = (size_t)kc * KCHUNK;
    const float4* Sp = (const float4*)S;

    if (tid < C) cnts[tid] = 0;
    __syncthreads();
    if (h == 0) {   // histogram counts (only half the CTAs)
        atomicAdd(&cnts[__ldg(L + rowbase + tid)], 1);
        atomicAdd(&cnts[__ldg(L + rowbase + 256 + tid)], 1);
    }

    float acc[4][2][4];
#pragma unroll
    for (int mt = 0; mt < 4; mt++)
#pragma unroll
        for (int nt = 0; nt < 2; nt++)
#pragma unroll
            for (int j = 0; j < 4; j++) acc[mt][nt][j] = 0.0f;

    float4 pf[8];
    // per-thread tile staging map: f = it*256+tid; trow = f>>5; col4 = f&31
    auto ldg_tile = [&](int t) {
#pragma unroll
        for (int it = 0; it < 8; it++) {
            int f = it * 256 + tid;
            int trow = f >> 5, col4 = f & 31;
            pf[it] = __ldg(Sp + (rowbase + t * TROWS + trow) * 64 + h * 32 + col4);
        }
    };
    auto sts_tile = [&](int buf) {
#pragma unroll
        for (int it = 0; it < 8; it++) {
            int f = it * 256 + tid;
            int trow = f >> 5, col4 = f & 31;
            __nv_bfloat162 p0 = __floats2bfloat162_rn(pf[it].x, pf[it].y);
            __nv_bfloat162 p1 = __floats2bfloat162_rn(pf[it].z, pf[it].w);
            uint2 u = { *(uint32_t*)&p0, *(uint32_t*)&p1 };
            uint32_t addr = buf * 16384 + trow * 256 +
                            ((((col4 >> 1) ^ (trow & 7))) << 4) + ((col4 & 1) << 3);
            *(uint2*)(smem_raw + addr) = u;
        }
    };
    auto ldg_labels = [&](int t, int buf) {
        if (tid < TROWS) labs[buf * 64 + tid] = __ldg(L + rowbase + t * TROWS + tid);
    };

    const unsigned base = lid >> 2;
    const int am = lid >> 3;
    auto mask_of = [&](int lab) -> unsigned {
        unsigned d = (unsigned)lab - base;
        return (d < 64u && !(d & 7u)) ? (1u << (d >> 3)) : 0u;
    };

    auto mma_tile = [&](int buf) {
        const int* lb = labs + buf * 64;
#pragma unroll
        for (int ks = 0; ks < 4; ks++) {
            int k0 = 2 * (lid & 3);
            int2 le = *(const int2*)(lb + ks * 16 + k0);
            int2 lo = *(const int2*)(lb + ks * 16 + k0 + 8);
            unsigned m0 = mask_of(le.x), m1 = mask_of(le.y);
            unsigned m2 = mask_of(lo.x), m3 = mask_of(lo.y);
            uint32_t areg[4][4];
#pragma unroll
            for (int mt = 0; mt < 4; mt++)
#pragma unroll
                for (int i = 0; i < 4; i++) {
                    unsigned jj = (i & 1) + 2 * mt;
                    unsigned me = (i >> 1) ? m2 : m0;
                    unsigned mo = (i >> 1) ? m3 : m1;
                    areg[mt][i] = ((me >> jj) & 1u) * 0x3F80u +
                                  ((mo >> jj) & 1u) * 0x3F800000u;
                }
            uint32_t f0, f1, f2, f3;
            {
                int trow = ks * 16 + (am & 1) * 8 + (lid & 7);
                uint32_t g = 2 * wid + (am >> 1);
                ldm4t(f0, f1, f2, f3,
                      sb + buf * 16384 + trow * 256 + (((g ^ (trow & 7))) << 4));
            }
#pragma unroll
            for (int mt = 0; mt < 4; mt++) {
                mma16816(acc[mt][0], areg[mt][0], areg[mt][1], areg[mt][2], areg[mt][3], f0, f1);
                mma16816(acc[mt][1], areg[mt][0], areg[mt][1], areg[mt][2], areg[mt][3], f2, f3);
            }
        }
    };

    ldg_tile(0);
    ldg_labels(0, 0);
    sts_tile(0);
    __syncthreads();

    for (int t = 0; t < 8; t++) {
        if (t + 1 < 8) { ldg_tile(t + 1); ldg_labels(t + 1, (t + 1) & 1); }
        mma_tile(t & 1);
        if (t + 1 < 8) sts_tile((t + 1) & 1);
        __syncthreads();
    }

    // ---- write partial [64][128] (plain streaming stores, no atomics) ----
    float* part = g_part + (size_t)blockIdx.x * 8192;
#pragma unroll
    for (int mt = 0; mt < 4; mt++)
#pragma unroll
        for (int nt = 0; nt < 2; nt++) {
            int r0 = 16 * mt + (lid >> 2);
            int dd = 16 * wid + 8 * nt + 2 * (lid & 3);
            float2 lo2 = { acc[mt][nt][0], acc[mt][nt][1] };
            float2 hi2 = { acc[mt][nt][2], acc[mt][nt][3] };
            __stcs((float2*)(part + r0 * 128 + dd), lo2);
            __stcs((float2*)(part + (r0 + 8) * 128 + dd), hi2);
        }
    if (h == 0 && tid < C) atomicAdd(&g_cnt[tid], cnts[tid]);
}

// ---------------- finalize: reduce partials, normalize, bf16 swizzle ----------------
// 64 blocks (one per class) x 256 threads (one per dim)
__global__ void __launch_bounds__(256) k_fin2() {
    __shared__ float red[256];
    const int c = blockIdx.x, t = threadIdx.x;
    const int h = t >> 7, dl = t & 127;
    const float* src = g_part + h * 8192 + c * 128 + dl;
    float s = 0.0f;
#pragma unroll 8
    for (int k = 0; k < 512; k++) s += __ldg(src + (size_t)k * 16384);

    float inv_d = 1.0f / fmaxf((float)g_cnt[c], 1.0f);
    float p = s * inv_d;
    red[t] = p * p;
    __syncthreads();
    for (int st = 128; st > 0; st >>= 1) {
        if (t < st) red[t] += red[t + st];
        __syncthreads();
    }
    float inv = 1.0f / fmaxf(sqrtf(red[0]), 1e-8f);
    uint32_t byte = (uint32_t)(c * 512 + ((((t >> 3) ^ (c & 7))) << 4) + (t & 7) * 2);
    ((__nv_bfloat16*)g_Pbf4)[byte >> 1] = __float2bfloat16_rn(p * inv);
}

// fast exp on the FMA pipe
__device__ __forceinline__ float fexp(float x) {
    float y = x * 1.442695041f;
    float r = y + 12582912.0f;
    int n = __float_as_int(r) - 0x4B400000;
    float f = y - (r - 12582912.0f);
    float p = 1.3333558e-3f;
    p = fmaf(p, f, 9.6181291e-3f);
    p = fmaf(p, f, 5.5504109e-2f);
    p = fmaf(p, f, 2.4022651e-1f);
    p = fmaf(p, f, 6.9314718e-1f);
    p = fmaf(p, f, 1.0f);
    return __int_as_float(__float_as_int(p) + (n << 23));
}

// ---------------- query kernel: R4 winner, verbatim ----------------
#define OFF_QSS  0
#define OFF_B    512
#define OFF_A    33280
#define SMEM_QRY (OFF_A + MT * 512)

__global__ void __launch_bounds__(256, 2) k_query(const float* __restrict__ Q,
                                                  float* __restrict__ out) {
    uint32_t sb = smem_u32(smem_raw);
    float* qss = (float*)(smem_raw + OFF_QSS);
    const int tid = threadIdx.x;
    const int wid = tid >> 5;
    const int lid = tid & 31;
    const int qbase = blockIdx.x * MT;

    if (tid < MT) qss[tid] = 0.0f;

#pragma unroll
    for (int it = 0; it < 8; it++)
        ((uint4*)(smem_raw + OFF_B))[tid + it * 256] = g_Pbf4[tid + it * 256];

    __syncthreads();

#pragma unroll
    for (int it = 0; it < 32; it++) {
        int f = it * 256 + tid;
        int row = f >> 6;
        int col4 = f & 63;
        float4 v = __ldg(((const float4*)Q) + (size_t)(qbase + row) * (D / 4) + col4);
        __nv_bfloat162 p0 = __floats2bfloat162_rn(v.x, v.y);
        __nv_bfloat162 p1 = __floats2bfloat162_rn(v.z, v.w);
        uint2 u = { *(uint32_t*)&p0, *(uint32_t*)&p1 };
        uint32_t addr = OFF_A + row * 512 + ((((col4 >> 1) ^ (row & 7))) << 4) + ((col4 & 1) << 3);
        *(uint2*)(smem_raw + addr) = u;
        float s = v.x * v.x + v.y * v.y + v.z * v.z + v.w * v.w;
#pragma unroll
        for (int w = 16; w > 0; w >>= 1) s += __shfl_xor_sync(0xffffffffu, s, w);
        if (lid == 0) atomicAdd(&qss[row], s);
    }
    __syncthreads();

    float dacc[8][4];
#pragma unroll
    for (int nt = 0; nt < 8; nt++)
#pragma unroll
        for (int j = 0; j < 4; j++) dacc[nt][j] = 0.0f;

    const int am   = lid >> 3;
    const int arow = wid * 16 + (am & 1) * 8 + (lid & 7);
    const int agsel = am >> 1;
    const int brow0 = (am >> 1) * 8 + (lid & 7);
    const int bgsel = am & 1;

#pragma unroll
    for (int s = 0; s < 16; s++) {
        uint32_t a0, a1, a2, a3;
        {
            uint32_t g = 2 * s + agsel;
            uint32_t addr = sb + OFF_A + arow * 512 + (((g ^ (arow & 7))) << 4);
            ldm4(a0, a1, a2, a3, addr);
        }
        uint32_t bfr[16];
#pragma unroll
        for (int pp = 0; pp < 4; pp++) {
            int row = pp * 16 + brow0;
            uint32_t g = 2 * s + bgsel;
            uint32_t addr = sb + OFF_B + row * 512 + (((g ^ (row & 7))) << 4);
            ldm4(bfr[pp * 4 + 0], bfr[pp * 4 + 1], bfr[pp * 4 + 2], bfr[pp * 4 + 3], addr);
        }
#pragma unroll
        for (int nt = 0; nt < 8; nt++)
            mma16816(dacc[nt], a0, a1, a2, a3, bfr[nt * 2], bfr[nt * 2 + 1]);
    }

    float dA[16], dB[16];
#pragma unroll
    for (int nt = 0; nt < 8; nt++) {
        dA[nt * 2] = dacc[nt][0]; dA[nt * 2 + 1] = dacc[nt][1];
        dB[nt * 2] = dacc[nt][2]; dB[nt * 2 + 1] = dacc[nt][3];
    }
    const int rA = wid * 16 + (lid >> 2);
    const int rB = rA + 8;
    float invA = 1.0f / fmaxf(sqrtf(qss[rA]), 1e-8f);
    float invB = 1.0f / fmaxf(sqrtf(qss[rB]), 1e-8f);

    float mA = -3.4e38f, mB = -3.4e38f;
#pragma unroll
    for (int j = 0; j < 16; j++) {
        dA[j] *= invA; mA = fmaxf(mA, dA[j]);
        dB[j] *= invB; mB = fmaxf(mB, dB[j]);
    }
#pragma unroll
    for (int w = 1; w < 4; w <<= 1) {
        mA = fmaxf(mA, __shfl_xor_sync(0xffffffffu, mA, w));
        mB = fmaxf(mB, __shfl_xor_sync(0xffffffffu, mB, w));
    }
    float sA = 0.0f, sB = 0.0f;
#pragma unroll
    for (int j = 0; j < 16; j++) {
        sA += fexp(dA[j] - mA);
        sB += fexp(dB[j] - mB);
    }
#pragma unroll
    for (int w = 1; w < 4; w <<= 1) {
        sA += __shfl_xor_sync(0xffffffffu, sA, w);
        sB += __shfl_xor_sync(0xffffffffu, sB, w);
    }
    float lseA = mA + logf(sA);
    float lseB = mB + logf(sB);

    float* oA = out + (size_t)(qbase + rA) * C + (lid & 3) * 2;
    float* oB = out + (size_t)(qbase + rB) * C + (lid & 3) * 2;
#pragma unroll
    for (int nt = 0; nt < 8; nt++) {
        float2 a = { dA[nt * 2] - lseA, dA[nt * 2 + 1] - lseA };
        float2 b = { dB[nt * 2] - lseB, dB[nt * 2 + 1] - lseB };
        *(float2*)(oA + nt * 8) = a;
        *(float2*)(oB + nt * 8) = b;
    }
}

extern "C" void kernel_launch(void* const* d_in, const int* in_sizes, int n_in,
                              void* d_out, int out_size) {
    const float* support = (const float*)d_in[0];
    const int*   labels  = (const int*)d_in[1];
    const float* query   = (const float*)d_in[2];
    float*       out     = (float*)d_out;

    cudaFuncSetAttribute(k_seg,   cudaFuncAttributeMaxDynamicSharedMemorySize, SEG_SMEM);
    cudaFuncSetAttribute(k_query, cudaFuncAttributeMaxDynamicSharedMemorySize, SMEM_QRY);

    k_zero<<<1, 256>>>();
    k_seg<<<1024, 256, SEG_SMEM>>>(support, labels);
    k_fin2<<<C, 256>>>();
    k_query<<<NQ / MT, 256, SMEM_QRY>>>(query, out);
}

// round 8
// speedup vs baseline: 1.8070x; 1.2660x over previous
#include <cuda_runtime.h>
#include <cuda_bf16.h>
#include <math.h>
#include <stdint.h>

#define NQ 131072
#define NS 262144
#define D  256
#define C  64
#define MT 128

// ---------------- device scratch ----------------
__device__ int   g_cnt[C];
__device__ uint4 g_Pbf4[2048];              // 32KB: prototypes bf16, swizzled, /p_norm
__device__ float g_part[1024 * 8192];       // 32MB: per-CTA partial [64][128]
__device__ float g_red[16 * 8192];          // 512KB: stage-1 reduced partials

extern __shared__ char smem_raw[];

__device__ __forceinline__ uint32_t smem_u32(const void* p) {
    uint32_t a;
    asm("{ .reg .u64 t; cvta.to.shared.u64 t, %1; cvt.u32.u64 %0, t; }" : "=r"(a) : "l"(p));
    return a;
}
__device__ __forceinline__ void ldm4(uint32_t& r0, uint32_t& r1, uint32_t& r2, uint32_t& r3,
                                     uint32_t addr) {
    asm volatile("ldmatrix.sync.aligned.m8n8.x4.shared.b16 {%0,%1,%2,%3}, [%4];"
                 : "=r"(r0), "=r"(r1), "=r"(r2), "=r"(r3) : "r"(addr));
}
__device__ __forceinline__ void ldm4t(uint32_t& r0, uint32_t& r1, uint32_t& r2, uint32_t& r3,
                                      uint32_t addr) {
    asm volatile("ldmatrix.sync.aligned.m8n8.x4.trans.shared.b16 {%0,%1,%2,%3}, [%4];"
                 : "=r"(r0), "=r"(r1), "=r"(r2), "=r"(r3) : "r"(addr));
}
__device__ __forceinline__ void mma16816(float* d, uint32_t a0, uint32_t a1, uint32_t a2,
                                         uint32_t a3, uint32_t b0, uint32_t b1) {
    asm volatile("mma.sync.aligned.m16n8k16.row.col.f32.bf16.bf16.f32 "
                 "{%0,%1,%2,%3}, {%4,%5,%6,%7}, {%8,%9}, {%0,%1,%2,%3};"
                 : "+f"(d[0]), "+f"(d[1]), "+f"(d[2]), "+f"(d[3])
                 : "r"(a0), "r"(a1), "r"(a2), "r"(a3), "r"(b0), "r"(b1));
}

// ---------------- zero counts ----------------
__global__ void k_zero() {
    int i = blockIdx.x * blockDim.x + threadIdx.x;
    if (i < C) g_cnt[i] = 0;
}

// ---------------- segment sum as GEMM: partial[c][d] = OneHot^T @ S ----------------
// 1024 CTAs: kc = b>>1 (512 rows), h = b&1 (dim half). 256 thr, 8 warps x 16 dims.
// smem: S double buf 2x16KB @0, onehot [64c][64r] bf16 8KB @32768 (swizzled),
//       labels[2][64] @40960, cnt @41472
#define KCHUNK   512
#define TROWS    64
#define OFF_OH   32768
#define OFF_LAB  40960
#define OFF_CNT  41472
#define SEG_SMEM (OFF_CNT + 256)

__global__ void __launch_bounds__(256, 2) k_seg(const float* __restrict__ S,
                                                const int* __restrict__ L) {
    uint32_t sb = smem_u32(smem_raw);
    int* labs = (int*)(smem_raw + OFF_LAB);
    int* cnts = (int*)(smem_raw + OFF_CNT);
    const int tid = threadIdx.x;
    const int wid = tid >> 5;
    const int lid = tid & 31;
    const int kc  = blockIdx.x >> 1;
    const int h   = blockIdx.x & 1;
    const size_t rowbase = (size_t)kc * KCHUNK;
    const float4* Sp = (const float4*)S;

    if (tid < C) cnts[tid] = 0;
    // zero onehot (8KB)
#pragma unroll
    for (int i = 0; i < 2; i++)
        ((uint4*)(smem_raw + OFF_OH))[tid + i * 256] = make_uint4(0, 0, 0, 0);
    __syncthreads();
    if (h == 0) {
        atomicAdd(&cnts[__ldg(L + rowbase + tid)], 1);
        atomicAdd(&cnts[__ldg(L + rowbase + 256 + tid)], 1);
    }

    float acc[4][2][4];
#pragma unroll
    for (int mt = 0; mt < 4; mt++)
#pragma unroll
        for (int nt = 0; nt < 2; nt++)
#pragma unroll
            for (int j = 0; j < 4; j++) acc[mt][nt][j] = 0.0f;

    float4 pf[8];
    auto ldg_tile = [&](int t) {
#pragma unroll
        for (int it = 0; it < 8; it++) {
            int f = it * 256 + tid;
            int trow = f >> 5, col4 = f & 31;
            pf[it] = __ldg(Sp + (rowbase + t * TROWS + trow) * 64 + h * 32 + col4);
        }
    };
    auto sts_tile = [&](int buf) {
#pragma unroll
        for (int it = 0; it < 8; it++) {
            int f = it * 256 + tid;
            int trow = f >> 5, col4 = f & 31;
            __nv_bfloat162 p0 = __floats2bfloat162_rn(pf[it].x, pf[it].y);
            __nv_bfloat162 p1 = __floats2bfloat162_rn(pf[it].z, pf[it].w);
            uint2 u = { *(uint32_t*)&p0, *(uint32_t*)&p1 };
            uint32_t addr = buf * 16384 + trow * 256 +
                            ((((col4 >> 1) ^ (trow & 7))) << 4) + ((col4 & 1) << 3);
            *(uint2*)(smem_raw + addr) = u;
        }
    };
    auto ldg_labels = [&](int t, int buf) {
        if (tid < TROWS) labs[buf * 64 + tid] = __ldg(L + rowbase + t * TROWS + tid);
    };

    // onehot scatter state: thread tid<64 owns tile-row r=tid
    uint32_t oldaddr = 0xFFFFFFFFu;
    const unsigned short one_bf = 0x3F80u;
    auto scatter = [&](int buf) {
        if (tid < TROWS) {
            int lab = labs[buf * 64 + tid];
            // oh[c][r]: addr = c*128 + swz granule(r>>3) + (r&7)*2
            uint32_t addr = OFF_OH + lab * 128 + ((((tid >> 3) ^ (lab & 7))) << 4) + (tid & 7) * 2;
            if (oldaddr != 0xFFFFFFFFu) *(unsigned short*)(smem_raw + oldaddr) = 0;
            *(unsigned short*)(smem_raw + addr) = one_bf;
            oldaddr = addr;
        }
    };

    const int am    = lid >> 3;
    const int mrow0 = (am & 1) * 8 + (lid & 7);   // A local m row
    const int agsel = am >> 1;                    // A k-granule half
    auto mma_tile = [&](int buf) {
#pragma unroll
        for (int ks = 0; ks < 4; ks++) {
            uint32_t a[4][4];
#pragma unroll
            for (int mt = 0; mt < 4; mt++) {
                int m = mt * 16 + mrow0;
                uint32_t g = ks * 2 + agsel;
                ldm4(a[mt][0], a[mt][1], a[mt][2], a[mt][3],
                     sb + OFF_OH + m * 128 + (((g ^ (m & 7))) << 4));
            }
            uint32_t f0, f1, f2, f3;
            {
                int trow = ks * 16 + (am & 1) * 8 + (lid & 7);
                uint32_t g = 2 * wid + (am >> 1);
                ldm4t(f0, f1, f2, f3,
                      sb + buf * 16384 + trow * 256 + (((g ^ (trow & 7))) << 4));
            }
#pragma unroll
            for (int mt = 0; mt < 4; mt++) {
                mma16816(acc[mt][0], a[mt][0], a[mt][1], a[mt][2], a[mt][3], f0, f1);
                mma16816(acc[mt][1], a[mt][0], a[mt][1], a[mt][2], a[mt][3], f2, f3);
            }
        }
    };

    ldg_tile(0);
    ldg_labels(0, 0);
    sts_tile(0);
    __syncthreads();

    for (int t = 0; t < 8; t++) {
        scatter(t & 1);                                        // needs labs(t); mma(t-1) done
        if (t + 1 < 8) { ldg_tile(t + 1); ldg_labels(t + 1, (t + 1) & 1); }
        __syncthreads();                                       // onehot ready
        mma_tile(t & 1);
        if (t + 1 < 8) sts_tile((t + 1) & 1);
        __syncthreads();                                       // mma done before next scatter
    }

    // ---- write partial [64][128] ----
    float* part = g_part + (size_t)blockIdx.x * 8192;
#pragma unroll
    for (int mt = 0; mt < 4; mt++)
#pragma unroll
        for (int nt = 0; nt < 2; nt++) {
            int r0 = 16 * mt + (lid >> 2);
            int dd = 16 * wid + 8 * nt + 2 * (lid & 3);
            float2 lo2 = { acc[mt][nt][0], acc[mt][nt][1] };
            float2 hi2 = { acc[mt][nt][2], acc[mt][nt][3] };
            __stcs((float2*)(part + r0 * 128 + dd), lo2);
            __stcs((float2*)(part + (r0 + 8) * 128 + dd), hi2);
        }
    if (h == 0 && tid < C) atomicAdd(&g_cnt[tid], cnts[tid]);
}

// ---------------- stage-1 reduce: 1024 partials -> 16 (parity-preserving) ----------------
// grid 512: CTA = (h, gg, slice): h = b>>8, gg = (b>>5)&7, slice = b&31.
// Each (h,gg) covers kc = gg*64 .. gg*64+63  (j<64) -> all 512 kc per parity.
__global__ void __launch_bounds__(256) k_red() {
    const int slice = blockIdx.x & 31;
    const int gg    = (blockIdx.x >> 5) & 7;
    const int h     = blockIdx.x >> 8;
    const int e     = slice * 256 + threadIdx.x;
    const float* src = g_part + (size_t)((gg * 64) * 2 + h) * 8192 + e;
    float s = 0.0f;
#pragma unroll 8
    for (int j = 0; j < 64; j++) s += __ldg(src + (size_t)j * 16384);
    g_red[(h * 8 + gg) * 8192 + e] = s;
}

// ---------------- finalize: reduce 16, normalize, bf16 swizzle ----------------
__global__ void __launch_bounds__(256) k_fin2() {
    __shared__ float red[256];
    const int c = blockIdx.x, t = threadIdx.x;
    const int h = t >> 7, dl = t & 127;
    const float* src = g_red + (size_t)h * 8 * 8192 + c * 128 + dl;
    float s = 0.0f;
#pragma unroll
    for (int g = 0; g < 8; g++) s += __ldg(src + (size_t)g * 8192);

    float inv_d = 1.0f / fmaxf((float)g_cnt[c], 1.0f);
    float p = s * inv_d;
    red[t] = p * p;
    __syncthreads();
    for (int st = 128; st > 0; st >>= 1) {
        if (t < st) red[t] += red[t + st];
        __syncthreads();
    }
    float inv = 1.0f / fmaxf(sqrtf(red[0]), 1e-8f);
    uint32_t byte = (uint32_t)(c * 512 + ((((t >> 3) ^ (c & 7))) << 4) + (t & 7) * 2);
    ((__nv_bfloat16*)g_Pbf4)[byte >> 1] = __float2bfloat16_rn(p * inv);
}

// fast exp on the FMA pipe
__device__ __forceinline__ float fexp(float x) {
    float y = x * 1.442695041f;
    float r = y + 12582912.0f;
    int n = __float_as_int(r) - 0x4B400000;
    float f = y - (r - 12582912.0f);
    float p = 1.3333558e-3f;
    p = fmaf(p, f, 9.6181291e-3f);
    p = fmaf(p, f, 5.5504109e-2f);
    p = fmaf(p, f, 2.4022651e-1f);
    p = fmaf(p, f, 6.9314718e-1f);
    p = fmaf(p, f, 1.0f);
    return __int_as_float(__float_as_int(p) + (n << 23));
}

// ---------------- query kernel: R4 winner, verbatim ----------------
#define OFF_QSS  0
#define OFF_B    512
#define OFF_A    33280
#define SMEM_QRY (OFF_A + MT * 512)

__global__ void __launch_bounds__(256, 2) k_query(const float* __restrict__ Q,
                                                  float* __restrict__ out) {
    uint32_t sb = smem_u32(smem_raw);
    float* qss = (float*)(smem_raw + OFF_QSS);
    const int tid = threadIdx.x;
    const int wid = tid >> 5;
    const int lid = tid & 31;
    const int qbase = blockIdx.x * MT;

    if (tid < MT) qss[tid] = 0.0f;

#pragma unroll
    for (int it = 0; it < 8; it++)
        ((uint4*)(smem_raw + OFF_B))[tid + it * 256] = g_Pbf4[tid + it * 256];

    __syncthreads();

#pragma unroll
    for (int it = 0; it < 32; it++) {
        int f = it * 256 + tid;
        int row = f >> 6;
        int col4 = f & 63;
        float4 v = __ldg(((const float4*)Q) + (size_t)(qbase + row) * (D / 4) + col4);
        __nv_bfloat162 p0 = __floats2bfloat162_rn(v.x, v.y);
        __nv_bfloat162 p1 = __floats2bfloat162_rn(v.z, v.w);
        uint2 u = { *(uint32_t*)&p0, *(uint32_t*)&p1 };
        uint32_t addr = OFF_A + row * 512 + ((((col4 >> 1) ^ (row & 7))) << 4) + ((col4 & 1) << 3);
        *(uint2*)(smem_raw + addr) = u;
        float s = v.x * v.x + v.y * v.y + v.z * v.z + v.w * v.w;
#pragma unroll
        for (int w = 16; w > 0; w >>= 1) s += __shfl_xor_sync(0xffffffffu, s, w);
        if (lid == 0) atomicAdd(&qss[row], s);
    }
    __syncthreads();

    float dacc[8][4];
#pragma unroll
    for (int nt = 0; nt < 8; nt++)
#pragma unroll
        for (int j = 0; j < 4; j++) dacc[nt][j] = 0.0f;

    const int am   = lid >> 3;
    const int arow = wid * 16 + (am & 1) * 8 + (lid & 7);
    const int agsel = am >> 1;
    const int brow0 = (am >> 1) * 8 + (lid & 7);
    const int bgsel = am & 1;

#pragma unroll
    for (int s = 0; s < 16; s++) {
        uint32_t a0, a1, a2, a3;
        {
            uint32_t g = 2 * s + agsel;
            uint32_t addr = sb + OFF_A + arow * 512 + (((g ^ (arow & 7))) << 4);
            ldm4(a0, a1, a2, a3, addr);
        }
        uint32_t bfr[16];
#pragma unroll
        for (int pp = 0; pp < 4; pp++) {
            int row = pp * 16 + brow0;
            uint32_t g = 2 * s + bgsel;
            uint32_t addr = sb + OFF_B + row * 512 + (((g ^ (row & 7))) << 4);
            ldm4(bfr[pp * 4 + 0], bfr[pp * 4 + 1], bfr[pp * 4 + 2], bfr[pp * 4 + 3], addr);
        }
#pragma unroll
        for (int nt = 0; nt < 8; nt++)
            mma16816(dacc[nt], a0, a1, a2, a3, bfr[nt * 2], bfr[nt * 2 + 1]);
    }

    float dA[16], dB[16];
#pragma unroll
    for (int nt = 0; nt < 8; nt++) {
        dA[nt * 2] = dacc[nt][0]; dA[nt * 2 + 1] = dacc[nt][1];
        dB[nt * 2] = dacc[nt][2]; dB[nt * 2 + 1] = dacc[nt][3];
    }
    const int rA = wid * 16 + (lid >> 2);
    const int rB = rA + 8;
    float invA = 1.0f / fmaxf(sqrtf(qss[rA]), 1e-8f);
    float invB = 1.0f / fmaxf(sqrtf(qss[rB]), 1e-8f);

    float mA = -3.4e38f, mB = -3.4e38f;
#pragma unroll
    for (int j = 0; j < 16; j++) {
        dA[j] *= invA; mA = fmaxf(mA, dA[j]);
        dB[j] *= invB; mB = fmaxf(mB, dB[j]);
    }
#pragma unroll
    for (int w = 1; w < 4; w <<= 1) {
        mA = fmaxf(mA, __shfl_xor_sync(0xffffffffu, mA, w));
        mB = fmaxf(mB, __shfl_xor_sync(0xffffffffu, mB, w));
    }
    float sA = 0.0f, sB = 0.0f;
#pragma unroll
    for (int j = 0; j < 16; j++) {
        sA += fexp(dA[j] - mA);
        sB += fexp(dB[j] - mB);
    }
#pragma unroll
    for (int w = 1; w < 4; w <<= 1) {
        sA += __shfl_xor_sync(0xffffffffu, sA, w);
        sB += __shfl_xor_sync(0xffffffffu, sB, w);
    }
    float lseA = mA + logf(sA);
    float lseB = mB + logf(sB);

    float* oA = out + (size_t)(qbase + rA) * C + (lid & 3) * 2;
    float* oB = out + (size_t)(qbase + rB) * C + (lid & 3) * 2;
#pragma unroll
    for (int nt = 0; nt < 8; nt++) {
        float2 a = { dA[nt * 2] - lseA, dA[nt * 2 + 1] - lseA };
        float2 b = { dB[nt * 2] - lseB, dB[nt * 2 + 1] - lseB };
        *(float2*)(oA + nt * 8) = a;
        *(float2*)(oB + nt * 8) = b;
    }
}

extern "C" void kernel_launch(void* const* d_in, const int* in_sizes, int n_in,
                              void* d_out, int out_size) {
    const float* support = (const float*)d_in[0];
    const int*   labels  = (const int*)d_in[1];
    const float* query   = (const float*)d_in[2];
    float*       out     = (float*)d_out;

    cudaFuncSetAttribute(k_seg,   cudaFuncAttributeMaxDynamicSharedMemorySize, SEG_SMEM);
    cudaFuncSetAttribute(k_query, cudaFuncAttributeMaxDynamicSharedMemorySize, SMEM_QRY);

    k_zero<<<1, 256>>>();
    k_seg<<<1024, 256, SEG_SMEM>>>(support, labels);
    k_red<<<512, 256>>>();
    k_fin2<<<C, 256>>>();
    k_query<<<NQ / MT, 256, SMEM_QRY>>>(query, out);
}

// round 9
// speedup vs baseline: 2.0083x; 1.1114x over previous
#include <cuda_runtime.h>
#include <cuda_bf16.h>
#include <math.h>
#include <stdint.h>

#define NQ 131072
#define NS 262144
#define D  256
#define C  64
#define MT 128

// ---------------- device scratch ----------------
__device__ int   g_cnt[C];
__device__ uint4 g_Pbf4[2048];              // 32KB: prototypes bf16, swizzled, /p_norm
__device__ float g_part[1024 * 8192];       // 32MB: per-CTA partial [64][128]
__device__ float g_red[16 * 8192];          // 512KB: stage-1 reduced partials

extern __shared__ char smem_raw[];

__device__ __forceinline__ uint32_t smem_u32(const void* p) {
    uint32_t a;
    asm("{ .reg .u64 t; cvta.to.shared.u64 t, %1; cvt.u32.u64 %0, t; }" : "=r"(a) : "l"(p));
    return a;
}
__device__ __forceinline__ void ldm4(uint32_t& r0, uint32_t& r1, uint32_t& r2, uint32_t& r3,
                                     uint32_t addr) {
    asm volatile("ldmatrix.sync.aligned.m8n8.x4.shared.b16 {%0,%1,%2,%3}, [%4];"
                 : "=r"(r0), "=r"(r1), "=r"(r2), "=r"(r3) : "r"(addr));
}
__device__ __forceinline__ void ldm4t(uint32_t& r0, uint32_t& r1, uint32_t& r2, uint32_t& r3,
                                      uint32_t addr) {
    asm volatile("ldmatrix.sync.aligned.m8n8.x4.trans.shared.b16 {%0,%1,%2,%3}, [%4];"
                 : "=r"(r0), "=r"(r1), "=r"(r2), "=r"(r3) : "r"(addr));
}
__device__ __forceinline__ void mma16816(float* d, uint32_t a0, uint32_t a1, uint32_t a2,
                                         uint32_t a3, uint32_t b0, uint32_t b1) {
    asm volatile("mma.sync.aligned.m16n8k16.row.col.f32.bf16.bf16.f32 "
                 "{%0,%1,%2,%3}, {%4,%5,%6,%7}, {%8,%9}, {%0,%1,%2,%3};"
                 : "+f"(d[0]), "+f"(d[1]), "+f"(d[2]), "+f"(d[3])
                 : "r"(a0), "r"(a1), "r"(a2), "r"(a3), "r"(b0), "r"(b1));
}

// ---------------- zero counts ----------------
__global__ void k_zero() {
    int i = blockIdx.x * blockDim.x + threadIdx.x;
    if (i < C) g_cnt[i] = 0;
}

// ---------------- segment sum as GEMM: partial[c][d] = OneHot^T @ S ----------------
#define KCHUNK   512
#define TROWS    64
#define OFF_OH   32768
#define OFF_LAB  40960
#define OFF_CNT  41472
#define SEG_SMEM (OFF_CNT + 256)

__global__ void __launch_bounds__(256, 2) k_seg(const float* __restrict__ S,
                                                const int* __restrict__ L) {
    uint32_t sb = smem_u32(smem_raw);
    int* labs = (int*)(smem_raw + OFF_LAB);
    int* cnts = (int*)(smem_raw + OFF_CNT);
    const int tid = threadIdx.x;
    const int wid = tid >> 5;
    const int lid = tid & 31;
    const int kc  = blockIdx.x >> 1;
    const int h   = blockIdx.x & 1;
    const size_t rowbase = (size_t)kc * KCHUNK;
    const float4* Sp = (const float4*)S;

    if (tid < C) cnts[tid] = 0;
#pragma unroll
    for (int i = 0; i < 2; i++)
        ((uint4*)(smem_raw + OFF_OH))[tid + i * 256] = make_uint4(0, 0, 0, 0);
    __syncthreads();
    if (h == 0) {
        atomicAdd(&cnts[__ldg(L + rowbase + tid)], 1);
        atomicAdd(&cnts[__ldg(L + rowbase + 256 + tid)], 1);
    }

    float acc[4][2][4];
#pragma unroll
    for (int mt = 0; mt < 4; mt++)
#pragma unroll
        for (int nt = 0; nt < 2; nt++)
#pragma unroll
            for (int j = 0; j < 4; j++) acc[mt][nt][j] = 0.0f;

    float4 pf[8];
    auto ldg_tile = [&](int t) {
#pragma unroll
        for (int it = 0; it < 8; it++) {
            int f = it * 256 + tid;
            int trow = f >> 5, col4 = f & 31;
            pf[it] = __ldg(Sp + (rowbase + t * TROWS + trow) * 64 + h * 32 + col4);
        }
    };
    auto sts_tile = [&](int buf) {
#pragma unroll
        for (int it = 0; it < 8; it++) {
            int f = it * 256 + tid;
            int trow = f >> 5, col4 = f & 31;
            __nv_bfloat162 p0 = __floats2bfloat162_rn(pf[it].x, pf[it].y);
            __nv_bfloat162 p1 = __floats2bfloat162_rn(pf[it].z, pf[it].w);
            uint2 u = { *(uint32_t*)&p0, *(uint32_t*)&p1 };
            uint32_t addr = buf * 16384 + trow * 256 +
                            ((((col4 >> 1) ^ (trow & 7))) << 4) + ((col4 & 1) << 3);
            *(uint2*)(smem_raw + addr) = u;
        }
    };
    auto ldg_labels = [&](int t, int buf) {
        if (tid < TROWS) labs[buf * 64 + tid] = __ldg(L + rowbase + t * TROWS + tid);
    };

    uint32_t oldaddr = 0xFFFFFFFFu;
    const unsigned short one_bf = 0x3F80u;
    auto scatter = [&](int buf) {
        if (tid < TROWS) {
            int lab = labs[buf * 64 + tid];
            uint32_t addr = OFF_OH + lab * 128 + ((((tid >> 3) ^ (lab & 7))) << 4) + (tid & 7) * 2;
            if (oldaddr != 0xFFFFFFFFu) *(unsigned short*)(smem_raw + oldaddr) = 0;
            *(unsigned short*)(smem_raw + addr) = one_bf;
            oldaddr = addr;
        }
    };

    const int am    = lid >> 3;
    const int mrow0 = (am & 1) * 8 + (lid & 7);
    const int agsel = am >> 1;
    auto mma_tile = [&](int buf) {
#pragma unroll
        for (int ks = 0; ks < 4; ks++) {
            uint32_t a[4][4];
#pragma unroll
            for (int mt = 0; mt < 4; mt++) {
                int m = mt * 16 + mrow0;
                uint32_t g = ks * 2 + agsel;
                ldm4(a[mt][0], a[mt][1], a[mt][2], a[mt][3],
                     sb + OFF_OH + m * 128 + (((g ^ (m & 7))) << 4));
            }
            uint32_t f0, f1, f2, f3;
            {
                int trow = ks * 16 + (am & 1) * 8 + (lid & 7);
                uint32_t g = 2 * wid + (am >> 1);
                ldm4t(f0, f1, f2, f3,
                      sb + buf * 16384 + trow * 256 + (((g ^ (trow & 7))) << 4));
            }
#pragma unroll
            for (int mt = 0; mt < 4; mt++) {
                mma16816(acc[mt][0], a[mt][0], a[mt][1], a[mt][2], a[mt][3], f0, f1);
                mma16816(acc[mt][1], a[mt][0], a[mt][1], a[mt][2], a[mt][3], f2, f3);
            }
        }
    };

    ldg_tile(0);
    ldg_labels(0, 0);
    sts_tile(0);
    __syncthreads();

    for (int t = 0; t < 8; t++) {
        scatter(t & 1);
        if (t + 1 < 8) { ldg_tile(t + 1); ldg_labels(t + 1, (t + 1) & 1); }
        __syncthreads();
        mma_tile(t & 1);
        if (t + 1 < 8) sts_tile((t + 1) & 1);
        __syncthreads();
    }

    float* part = g_part + (size_t)blockIdx.x * 8192;
#pragma unroll
    for (int mt = 0; mt < 4; mt++)
#pragma unroll
        for (int nt = 0; nt < 2; nt++) {
            int r0 = 16 * mt + (lid >> 2);
            int dd = 16 * wid + 8 * nt + 2 * (lid & 3);
            float2 lo2 = { acc[mt][nt][0], acc[mt][nt][1] };
            float2 hi2 = { acc[mt][nt][2], acc[mt][nt][3] };
            __stcs((float2*)(part + r0 * 128 + dd), lo2);
            __stcs((float2*)(part + (r0 + 8) * 128 + dd), hi2);
        }
    if (h == 0 && tid < C) atomicAdd(&g_cnt[tid], cnts[tid]);
}

// ---------------- stage-1 reduce: 1024 partials -> 16 (parity-preserving) ----------------
__global__ void __launch_bounds__(256) k_red() {
    const int slice = blockIdx.x & 31;
    const int gg    = (blockIdx.x >> 5) & 7;
    const int h     = blockIdx.x >> 8;
    const int e     = slice * 256 + threadIdx.x;
    const float* src = g_part + (size_t)((gg * 64) * 2 + h) * 8192 + e;
    float s = 0.0f;
#pragma unroll 8
    for (int j = 0; j < 64; j++) s += __ldg(src + (size_t)j * 16384);
    g_red[(h * 8 + gg) * 8192 + e] = s;
}

// ---------------- finalize: reduce 16, normalize, bf16 swizzle ----------------
__global__ void __launch_bounds__(256) k_fin2() {
    __shared__ float red[256];
    const int c = blockIdx.x, t = threadIdx.x;
    const int h = t >> 7, dl = t & 127;
    const float* src = g_red + (size_t)h * 8 * 8192 + c * 128 + dl;
    float s = 0.0f;
#pragma unroll
    for (int g = 0; g < 8; g++) s += __ldg(src + (size_t)g * 8192);

    float inv_d = 1.0f / fmaxf((float)g_cnt[c], 1.0f);
    float p = s * inv_d;
    red[t] = p * p;
    __syncthreads();
    for (int st = 128; st > 0; st >>= 1) {
        if (t < st) red[t] += red[t + st];
        __syncthreads();
    }
    float inv = 1.0f / fmaxf(sqrtf(red[0]), 1e-8f);
    uint32_t byte = (uint32_t)(c * 512 + ((((t >> 3) ^ (c & 7))) << 4) + (t & 7) * 2);
    ((__nv_bfloat16*)g_Pbf4)[byte >> 1] = __float2bfloat16_rn(p * inv);
}

// fast exp on the FMA pipe
__device__ __forceinline__ float fexp(float x) {
    float y = x * 1.442695041f;
    float r = y + 12582912.0f;
    int n = __float_as_int(r) - 0x4B400000;
    float f = y - (r - 12582912.0f);
    float p = 1.3333558e-3f;
    p = fmaf(p, f, 9.6181291e-3f);
    p = fmaf(p, f, 5.5504109e-2f);
    p = fmaf(p, f, 2.4022651e-1f);
    p = fmaf(p, f, 6.9314718e-1f);
    p = fmaf(p, f, 1.0f);
    return __int_as_float(__float_as_int(p) + (n << 23));
}

// ---------------- query kernel v2: register-direct A fragments, no A staging ----------------
// 1024 CTAs x 256 thr; smem = B only (32KB) -> 3 CTAs/SM.
// Lane owns rows rA = wid*16 + (lid>>2), rB = rA+8; loads its own A fragments
// as sector-aligned float2 and accumulates its rows' sumsq on the fly.
#define SMEM_QRY 32768

__global__ void __launch_bounds__(256, 3) k_query(const float* __restrict__ Q,
                                                  float* __restrict__ out) {
    uint32_t sb = smem_u32(smem_raw);
    const int tid = threadIdx.x;
    const int wid = tid >> 5;
    const int lid = tid & 31;
    const int qbase = blockIdx.x * MT;

    // stage B (32KB pre-swizzled)
#pragma unroll
    for (int it = 0; it < 8; it++)
        ((uint4*)smem_raw)[tid + it * 256] = g_Pbf4[tid + it * 256];
    __syncthreads();

    const int rA = wid * 16 + (lid >> 2);
    const float* q0 = Q + (size_t)(qbase + rA) * D + 2 * (lid & 3);
    const float* q1 = q0 + 8 * D;

    const int brow0 = ((lid >> 3) >> 1) * 8 + (lid & 7);
    const int bgsel = (lid >> 3) & 1;

    float dacc[8][4];
#pragma unroll
    for (int nt = 0; nt < 8; nt++)
#pragma unroll
        for (int j = 0; j < 4; j++) dacc[nt][j] = 0.0f;

    float ssq0 = 0.0f, ssq1 = 0.0f;

    float2 c0, c1, c2, c3;          // current kstep fragments
    float2 n0, n1, n2, n3;          // prefetch
    c0 = __ldg((const float2*)(q0));
    c1 = __ldg((const float2*)(q1));
    c2 = __ldg((const float2*)(q0 + 8));
    c3 = __ldg((const float2*)(q1 + 8));

#pragma unroll
    for (int s = 0; s < 16; s++) {
        if (s < 15) {
            n0 = __ldg((const float2*)(q0 + (s + 1) * 16));
            n1 = __ldg((const float2*)(q1 + (s + 1) * 16));
            n2 = __ldg((const float2*)(q0 + (s + 1) * 16 + 8));
            n3 = __ldg((const float2*)(q1 + (s + 1) * 16 + 8));
        }
        ssq0 = fmaf(c0.x, c0.x, ssq0); ssq0 = fmaf(c0.y, c0.y, ssq0);
        ssq0 = fmaf(c2.x, c2.x, ssq0); ssq0 = fmaf(c2.y, c2.y, ssq0);
        ssq1 = fmaf(c1.x, c1.x, ssq1); ssq1 = fmaf(c1.y, c1.y, ssq1);
        ssq1 = fmaf(c3.x, c3.x, ssq1); ssq1 = fmaf(c3.y, c3.y, ssq1);

        __nv_bfloat162 ba0 = __floats2bfloat162_rn(c0.x, c0.y);
        __nv_bfloat162 ba1 = __floats2bfloat162_rn(c1.x, c1.y);
        __nv_bfloat162 ba2 = __floats2bfloat162_rn(c2.x, c2.y);
        __nv_bfloat162 ba3 = __floats2bfloat162_rn(c3.x, c3.y);
        uint32_t a0 = *(uint32_t*)&ba0, a1 = *(uint32_t*)&ba1;
        uint32_t a2 = *(uint32_t*)&ba2, a3 = *(uint32_t*)&ba3;

        uint32_t bfr[16];
#pragma unroll
        for (int pp = 0; pp < 4; pp++) {
            int row = pp * 16 + brow0;
            uint32_t g = 2 * s + bgsel;
            ldm4(bfr[pp * 4], bfr[pp * 4 + 1], bfr[pp * 4 + 2], bfr[pp * 4 + 3],
                 sb + row * 512 + (((g ^ (row & 7))) << 4));
        }
#pragma unroll
        for (int nt = 0; nt < 8; nt++)
            mma16816(dacc[nt], a0, a1, a2, a3, bfr[nt * 2], bfr[nt * 2 + 1]);

        c0 = n0; c1 = n1; c2 = n2; c3 = n3;
    }

    // quad-reduce sumsq (lanes of a quad cover disjoint col groups of same rows)
    ssq0 += __shfl_xor_sync(0xffffffffu, ssq0, 1);
    ssq0 += __shfl_xor_sync(0xffffffffu, ssq0, 2);
    ssq1 += __shfl_xor_sync(0xffffffffu, ssq1, 1);
    ssq1 += __shfl_xor_sync(0xffffffffu, ssq1, 2);

    float dA[16], dB[16];
#pragma unroll
    for (int nt = 0; nt < 8; nt++) {
        dA[nt * 2] = dacc[nt][0]; dA[nt * 2 + 1] = dacc[nt][1];
        dB[nt * 2] = dacc[nt][2]; dB[nt * 2 + 1] = dacc[nt][3];
    }
    float invA = 1.0f / fmaxf(sqrtf(ssq0), 1e-8f);
    float invB = 1.0f / fmaxf(sqrtf(ssq1), 1e-8f);

    float mA = -3.4e38f, mB = -3.4e38f;
#pragma unroll
    for (int j = 0; j < 16; j++) {
        dA[j] *= invA; mA = fmaxf(mA, dA[j]);
        dB[j] *= invB; mB = fmaxf(mB, dB[j]);
    }
#pragma unroll
    for (int w = 1; w < 4; w <<= 1) {
        mA = fmaxf(mA, __shfl_xor_sync(0xffffffffu, mA, w));
        mB = fmaxf(mB, __shfl_xor_sync(0xffffffffu, mB, w));
    }
    float sA = 0.0f, sB = 0.0f;
#pragma unroll
    for (int j = 0; j < 16; j++) {
        sA += fexp(dA[j] - mA);
        sB += fexp(dB[j] - mB);
    }
#pragma unroll
    for (int w = 1; w < 4; w <<= 1) {
        sA += __shfl_xor_sync(0xffffffffu, sA, w);
        sB += __shfl_xor_sync(0xffffffffu, sB, w);
    }
    float lseA = mA + logf(sA);
    float lseB = mB + logf(sB);

    float* oA = out + (size_t)(qbase + rA) * C + (lid & 3) * 2;
    float* oB = oA + 8 * C;
#pragma unroll
    for (int nt = 0; nt < 8; nt++) {
        float2 a = { dA[nt * 2] - lseA, dA[nt * 2 + 1] - lseA };
        float2 b = { dB[nt * 2] - lseB, dB[nt * 2 + 1] - lseB };
        *(float2*)(oA + nt * 8) = a;
        *(float2*)(oB + nt * 8) = b;
    }
}

extern "C" void kernel_launch(void* const* d_in, const int* in_sizes, int n_in,
                              void* d_out, int out_size) {
    const float* support = (const float*)d_in[0];
    const int*   labels  = (const int*)d_in[1];
    const float* query   = (const float*)d_in[2];
    float*       out     = (float*)d_out;

    cudaFuncSetAttribute(k_seg,   cudaFuncAttributeMaxDynamicSharedMemorySize, SEG_SMEM);
    cudaFuncSetAttribute(k_query, cudaFuncAttributeMaxDynamicSharedMemorySize, SMEM_QRY);

    k_zero<<<1, 256>>>();
    k_seg<<<1024, 256, SEG_SMEM>>>(support, labels);
    k_red<<<512, 256>>>();
    k_fin2<<<C, 256>>>();
    k_query<<<NQ / MT, 256, SMEM_QRY>>>(query, out);
}

// round 10
// speedup vs baseline: 2.0776x; 1.0345x over previous
#include <cuda_runtime.h>
#include <cuda_bf16.h>
#include <math.h>
#include <stdint.h>

#define NQ 131072
#define NS 262144
#define D  256
#define C  64
#define MT 128

// ---------------- device scratch ----------------
__device__ int   g_cnt[C];
__device__ uint4 g_Pbf4[2048];              // 32KB: prototypes bf16, swizzled, /p_norm
__device__ float g_part[512 * 8192];        // 16MB: per-CTA partial [64][128]
__device__ float g_red[8 * 8192];           // 256KB: stage-1 reduced partials

extern __shared__ char smem_raw[];

__device__ __forceinline__ uint32_t smem_u32(const void* p) {
    uint32_t a;
    asm("{ .reg .u64 t; cvta.to.shared.u64 t, %1; cvt.u32.u64 %0, t; }" : "=r"(a) : "l"(p));
    return a;
}
__device__ __forceinline__ void ldm4(uint32_t& r0, uint32_t& r1, uint32_t& r2, uint32_t& r3,
                                     uint32_t addr) {
    asm volatile("ldmatrix.sync.aligned.m8n8.x4.shared.b16 {%0,%1,%2,%3}, [%4];"
                 : "=r"(r0), "=r"(r1), "=r"(r2), "=r"(r3) : "r"(addr));
}
__device__ __forceinline__ void ldm4t(uint32_t& r0, uint32_t& r1, uint32_t& r2, uint32_t& r3,
                                      uint32_t addr) {
    asm volatile("ldmatrix.sync.aligned.m8n8.x4.trans.shared.b16 {%0,%1,%2,%3}, [%4];"
                 : "=r"(r0), "=r"(r1), "=r"(r2), "=r"(r3) : "r"(addr));
}
__device__ __forceinline__ void mma16816(float* d, uint32_t a0, uint32_t a1, uint32_t a2,
                                         uint32_t a3, uint32_t b0, uint32_t b1) {
    asm volatile("mma.sync.aligned.m16n8k16.row.col.f32.bf16.bf16.f32 "
                 "{%0,%1,%2,%3}, {%4,%5,%6,%7}, {%8,%9}, {%0,%1,%2,%3};"
                 : "+f"(d[0]), "+f"(d[1]), "+f"(d[2]), "+f"(d[3])
                 : "r"(a0), "r"(a1), "r"(a2), "r"(a3), "r"(b0), "r"(b1));
}

// ---------------- zero counts ----------------
__global__ void k_zero() {
    int i = blockIdx.x * blockDim.x + threadIdx.x;
    if (i < C) g_cnt[i] = 0;
}

// ---------------- segment sum as GEMM: partial[c][d] = OneHot^T @ S ----------------
// 512 CTAs: kc = b>>1 (1024 rows), h = b&1 (dim half). 16 tiles of 64 rows.
#define KCHUNK   1024
#define NTILES   16
#define TROWS    64
#define OFF_OH   32768
#define OFF_LAB  40960
#define OFF_CNT  41472
#define SEG_SMEM (OFF_CNT + 256)

__global__ void __launch_bounds__(256, 2) k_seg(const float* __restrict__ S,
                                                const int* __restrict__ L) {
    uint32_t sb = smem_u32(smem_raw);
    int* labs = (int*)(smem_raw + OFF_LAB);
    int* cnts = (int*)(smem_raw + OFF_CNT);
    const int tid = threadIdx.x;
    const int wid = tid >> 5;
    const int lid = tid & 31;
    const int kc  = blockIdx.x >> 1;
    const int h   = blockIdx.x & 1;
    const size_t rowbase = (size_t)kc * KCHUNK;
    const float4* Sp = (const float4*)S;

    if (tid < C) cnts[tid] = 0;
#pragma unroll
    for (int i = 0; i < 2; i++)
        ((uint4*)(smem_raw + OFF_OH))[tid + i * 256] = make_uint4(0, 0, 0, 0);
    __syncthreads();
    if (h == 0) {
#pragma unroll
        for (int j = 0; j < 4; j++)
            atomicAdd(&cnts[__ldg(L + rowbase + j * 256 + tid)], 1);
    }

    float acc[4][2][4];
#pragma unroll
    for (int mt = 0; mt < 4; mt++)
#pragma unroll
        for (int nt = 0; nt < 2; nt++)
#pragma unroll
            for (int j = 0; j < 4; j++) acc[mt][nt][j] = 0.0f;

    float4 pf[8];
    auto ldg_tile = [&](int t) {
#pragma unroll
        for (int it = 0; it < 8; it++) {
            int f = it * 256 + tid;
            int trow = f >> 5, col4 = f & 31;
            pf[it] = __ldg(Sp + (rowbase + t * TROWS + trow) * 64 + h * 32 + col4);
        }
    };
    auto sts_tile = [&](int buf) {
#pragma unroll
        for (int it = 0; it < 8; it++) {
            int f = it * 256 + tid;
            int trow = f >> 5, col4 = f & 31;
            __nv_bfloat162 p0 = __floats2bfloat162_rn(pf[it].x, pf[it].y);
            __nv_bfloat162 p1 = __floats2bfloat162_rn(pf[it].z, pf[it].w);
            uint2 u = { *(uint32_t*)&p0, *(uint32_t*)&p1 };
            uint32_t addr = buf * 16384 + trow * 256 +
                            ((((col4 >> 1) ^ (trow & 7))) << 4) + ((col4 & 1) << 3);
            *(uint2*)(smem_raw + addr) = u;
        }
    };
    auto ldg_labels = [&](int t, int buf) {
        if (tid < TROWS) labs[buf * 64 + tid] = __ldg(L + rowbase + t * TROWS + tid);
    };

    uint32_t oldaddr = 0xFFFFFFFFu;
    const unsigned short one_bf = 0x3F80u;
    auto scatter = [&](int buf) {
        if (tid < TROWS) {
            int lab = labs[buf * 64 + tid];
            uint32_t addr = OFF_OH + lab * 128 + ((((tid >> 3) ^ (lab & 7))) << 4) + (tid & 7) * 2;
            if (oldaddr != 0xFFFFFFFFu) *(unsigned short*)(smem_raw + oldaddr) = 0;
            *(unsigned short*)(smem_raw + addr) = one_bf;
            oldaddr = addr;
        }
    };

    const int am    = lid >> 3;
    const int mrow0 = (am & 1) * 8 + (lid & 7);
    const int agsel = am >> 1;
    auto mma_tile = [&](int buf) {
#pragma unroll
        for (int ks = 0; ks < 4; ks++) {
            uint32_t a[4][4];
#pragma unroll
            for (int mt = 0; mt < 4; mt++) {
                int m = mt * 16 + mrow0;
                uint32_t g = ks * 2 + agsel;
                ldm4(a[mt][0], a[mt][1], a[mt][2], a[mt][3],
                     sb + OFF_OH + m * 128 + (((g ^ (m & 7))) << 4));
            }
            uint32_t f0, f1, f2, f3;
            {
                int trow = ks * 16 + (am & 1) * 8 + (lid & 7);
                uint32_t g = 2 * wid + (am >> 1);
                ldm4t(f0, f1, f2, f3,
                      sb + buf * 16384 + trow * 256 + (((g ^ (trow & 7))) << 4));
            }
#pragma unroll
            for (int mt = 0; mt < 4; mt++) {
                mma16816(acc[mt][0], a[mt][0], a[mt][1], a[mt][2], a[mt][3], f0, f1);
                mma16816(acc[mt][1], a[mt][0], a[mt][1], a[mt][2], a[mt][3], f2, f3);
            }
        }
    };

    ldg_tile(0);
    ldg_labels(0, 0);
    sts_tile(0);
    __syncthreads();

    for (int t = 0; t < NTILES; t++) {
        scatter(t & 1);
        if (t + 1 < NTILES) { ldg_tile(t + 1); ldg_labels(t + 1, (t + 1) & 1); }
        __syncthreads();
        mma_tile(t & 1);
        if (t + 1 < NTILES) sts_tile((t + 1) & 1);
        __syncthreads();
    }

    float* part = g_part + (size_t)blockIdx.x * 8192;
#pragma unroll
    for (int mt = 0; mt < 4; mt++)
#pragma unroll
        for (int nt = 0; nt < 2; nt++) {
            int r0 = 16 * mt + (lid >> 2);
            int dd = 16 * wid + 8 * nt + 2 * (lid & 3);
            float2 lo2 = { acc[mt][nt][0], acc[mt][nt][1] };
            float2 hi2 = { acc[mt][nt][2], acc[mt][nt][3] };
            __stcs((float2*)(part + r0 * 128 + dd), lo2);
            __stcs((float2*)(part + (r0 + 8) * 128 + dd), hi2);
        }
    if (h == 0 && tid < C) atomicAdd(&g_cnt[tid], cnts[tid]);
}

// ---------------- stage-1 reduce: 512 partials -> 8 (parity-preserving) ----------------
// grid 256: CTA = (h, gg, slice): h = b>>7, gg = (b>>5)&3, slice = b&31.
// Each (h,gg) covers kc = gg*64 .. gg*64+63 -> all 256 kc per parity.
__global__ void __launch_bounds__(256) k_red() {
    const int slice = blockIdx.x & 31;
    const int gg    = (blockIdx.x >> 5) & 3;
    const int h     = blockIdx.x >> 7;
    const int e     = slice * 256 + threadIdx.x;
    const float* src = g_part + (size_t)((gg * 64) * 2 + h) * 8192 + e;
    float s = 0.0f;
#pragma unroll 8
    for (int j = 0; j < 64; j++) s += __ldg(src + (size_t)j * 16384);
    g_red[(h * 4 + gg) * 8192 + e] = s;
}

// ---------------- finalize: reduce 8, normalize, bf16 swizzle ----------------
__global__ void __launch_bounds__(256) k_fin2() {
    __shared__ float red[256];
    const int c = blockIdx.x, t = threadIdx.x;
    const int h = t >> 7, dl = t & 127;
    const float* src = g_red + (size_t)h * 4 * 8192 + c * 128 + dl;
    float s = 0.0f;
#pragma unroll
    for (int g = 0; g < 4; g++) s += __ldg(src + (size_t)g * 8192);

    float inv_d = 1.0f / fmaxf((float)g_cnt[c], 1.0f);
    float p = s * inv_d;
    red[t] = p * p;
    __syncthreads();
    for (int st = 128; st > 0; st >>= 1) {
        if (t < st) red[t] += red[t + st];
        __syncthreads();
    }
    float inv = 1.0f / fmaxf(sqrtf(red[0]), 1e-8f);
    uint32_t byte = (uint32_t)(c * 512 + ((((t >> 3) ^ (c & 7))) << 4) + (t & 7) * 2);
    ((__nv_bfloat16*)g_Pbf4)[byte >> 1] = __float2bfloat16_rn(p * inv);
}

// fast exp on the FMA pipe
__device__ __forceinline__ float fexp(float x) {
    float y = x * 1.442695041f;
    float r = y + 12582912.0f;
    int n = __float_as_int(r) - 0x4B400000;
    float f = y - (r - 12582912.0f);
    float p = 1.3333558e-3f;
    p = fmaf(p, f, 9.6181291e-3f);
    p = fmaf(p, f, 5.5504109e-2f);
    p = fmaf(p, f, 2.4022651e-1f);
    p = fmaf(p, f, 6.9314718e-1f);
    p = fmaf(p, f, 1.0f);
    return __int_as_float(__float_as_int(p) + (n << 23));
}

// ---------------- query kernel: R9 winner, verbatim ----------------
#define SMEM_QRY 32768

__global__ void __launch_bounds__(256, 3) k_query(const float* __restrict__ Q,
                                                  float* __restrict__ out) {
    uint32_t sb = smem_u32(smem_raw);
    const int tid = threadIdx.x;
    const int wid = tid >> 5;
    const int lid = tid & 31;
    const int qbase = blockIdx.x * MT;

#pragma unroll
    for (int it = 0; it < 8; it++)
        ((uint4*)smem_raw)[tid + it * 256] = g_Pbf4[tid + it * 256];
    __syncthreads();

    const int rA = wid * 16 + (lid >> 2);
    const float* q0 = Q + (size_t)(qbase + rA) * D + 2 * (lid & 3);
    const float* q1 = q0 + 8 * D;

    const int brow0 = ((lid >> 3) >> 1) * 8 + (lid & 7);
    const int bgsel = (lid >> 3) & 1;

    float dacc[8][4];
#pragma unroll
    for (int nt = 0; nt < 8; nt++)
#pragma unroll
        for (int j = 0; j < 4; j++) dacc[nt][j] = 0.0f;

    float ssq0 = 0.0f, ssq1 = 0.0f;

    float2 c0, c1, c2, c3;
    float2 n0, n1, n2, n3;
    c0 = __ldg((const float2*)(q0));
    c1 = __ldg((const float2*)(q1));
    c2 = __ldg((const float2*)(q0 + 8));
    c3 = __ldg((const float2*)(q1 + 8));

#pragma unroll
    for (int s = 0; s < 16; s++) {
        if (s < 15) {
            n0 = __ldg((const float2*)(q0 + (s + 1) * 16));
            n1 = __ldg((const float2*)(q1 + (s + 1) * 16));
            n2 = __ldg((const float2*)(q0 + (s + 1) * 16 + 8));
            n3 = __ldg((const float2*)(q1 + (s + 1) * 16 + 8));
        }
        ssq0 = fmaf(c0.x, c0.x, ssq0); ssq0 = fmaf(c0.y, c0.y, ssq0);
        ssq0 = fmaf(c2.x, c2.x, ssq0); ssq0 = fmaf(c2.y, c2.y, ssq0);
        ssq1 = fmaf(c1.x, c1.x, ssq1); ssq1 = fmaf(c1.y, c1.y, ssq1);
        ssq1 = fmaf(c3.x, c3.x, ssq1); ssq1 = fmaf(c3.y, c3.y, ssq1);

        __nv_bfloat162 ba0 = __floats2bfloat162_rn(c0.x, c0.y);
        __nv_bfloat162 ba1 = __floats2bfloat162_rn(c1.x, c1.y);
        __nv_bfloat162 ba2 = __floats2bfloat162_rn(c2.x, c2.y);
        __nv_bfloat162 ba3 = __floats2bfloat162_rn(c3.x, c3.y);
        uint32_t a0 = *(uint32_t*)&ba0, a1 = *(uint32_t*)&ba1;
        uint32_t a2 = *(uint32_t*)&ba2, a3 = *(uint32_t*)&ba3;

        uint32_t bfr[16];
#pragma unroll
        for (int pp = 0; pp < 4; pp++) {
            int row = pp * 16 + brow0;
            uint32_t g = 2 * s + bgsel;
            ldm4(bfr[pp * 4], bfr[pp * 4 + 1], bfr[pp * 4 + 2], bfr[pp * 4 + 3],
                 sb + row * 512 + (((g ^ (row & 7))) << 4));
        }
#pragma unroll
        for (int nt = 0; nt < 8; nt++)
            mma16816(dacc[nt], a0, a1, a2, a3, bfr[nt * 2], bfr[nt * 2 + 1]);

        c0 = n0; c1 = n1; c2 = n2; c3 = n3;
    }

    ssq0 += __shfl_xor_sync(0xffffffffu, ssq0, 1);
    ssq0 += __shfl_xor_sync(0xffffffffu, ssq0, 2);
    ssq1 += __shfl_xor_sync(0xffffffffu, ssq1, 1);
    ssq1 += __shfl_xor_sync(0xffffffffu, ssq1, 2);

    float dA[16], dB[16];
#pragma unroll
    for (int nt = 0; nt < 8; nt++) {
        dA[nt * 2] = dacc[nt][0]; dA[nt * 2 + 1] = dacc[nt][1];
        dB[nt * 2] = dacc[nt][2]; dB[nt * 2 + 1] = dacc[nt][3];
    }
    float invA = 1.0f / fmaxf(sqrtf(ssq0), 1e-8f);
    float invB = 1.0f / fmaxf(sqrtf(ssq1), 1e-8f);

    float mA = -3.4e38f, mB = -3.4e38f;
#pragma unroll
    for (int j = 0; j < 16; j++) {
        dA[j] *= invA; mA = fmaxf(mA, dA[j]);
        dB[j] *= invB; mB = fmaxf(mB, dB[j]);
    }
#pragma unroll
    for (int w = 1; w < 4; w <<= 1) {
        mA = fmaxf(mA, __shfl_xor_sync(0xffffffffu, mA, w));
        mB = fmaxf(mB, __shfl_xor_sync(0xffffffffu, mB, w));
    }
    float sA = 0.0f, sB = 0.0f;
#pragma unroll
    for (int j = 0; j < 16; j++) {
        sA += fexp(dA[j] - mA);
        sB += fexp(dB[j] - mB);
    }
#pragma unroll
    for (int w = 1; w < 4; w <<= 1) {
        sA += __shfl_xor_sync(0xffffffffu, sA, w);
        sB += __shfl_xor_sync(0xffffffffu, sB, w);
    }
    float lseA = mA + logf(sA);
    float lseB = mB + logf(sB);

    float* oA = out + (size_t)(qbase + rA) * C + (lid & 3) * 2;
    float* oB = oA + 8 * C;
#pragma unroll
    for (int nt = 0; nt < 8; nt++) {
        float2 a = { dA[nt * 2] - lseA, dA[nt * 2 + 1] - lseA };
        float2 b = { dB[nt * 2] - lseB, dB[nt * 2 + 1] - lseB };
        *(float2*)(oA + nt * 8) = a;
        *(float2*)(oB + nt * 8) = b;
    }
}

extern "C" void kernel_launch(void* const* d_in, const int* in_sizes, int n_in,
                              void* d_out, int out_size) {
    const float* support = (const float*)d_in[0];
    const int*   labels  = (const int*)d_in[1];
    const float* query   = (const float*)d_in[2];
    float*       out     = (float*)d_out;

    cudaFuncSetAttribute(k_seg,   cudaFuncAttributeMaxDynamicSharedMemorySize, SEG_SMEM);
    cudaFuncSetAttribute(k_query, cudaFuncAttributeMaxDynamicSharedMemorySize, SMEM_QRY);

    k_zero<<<1, 256>>>();
    k_seg<<<512, 256, SEG_SMEM>>>(support, labels);
    k_red<<<256, 256>>>();
    k_fin2<<<C, 256>>>();
    k_query<<<NQ / MT, 256, SMEM_QRY>>>(query, out);
}

// round 11
// speedup vs baseline: 2.1563x; 1.0379x over previous
#include <cuda_runtime.h>
#include <cuda_bf16.h>
#include <math.h>
#include <stdint.h>

#define NQ 131072
#define NS 262144
#define D  256
#define C  64
#define MT 128

// ---------------- device scratch ----------------
__device__ int   g_cnt[C];
__device__ uint4 g_Pbf4[2048];              // 32KB: prototypes bf16, swizzled+k-permuted, /p_norm
__device__ float g_part[512 * 8192];        // 16MB: per-CTA partial [64][128]
__device__ float g_red[8 * 8192];           // 256KB: stage-1 reduced partials

extern __shared__ char smem_raw[];

__device__ __forceinline__ uint32_t smem_u32(const void* p) {
    uint32_t a;
    asm("{ .reg .u64 t; cvta.to.shared.u64 t, %1; cvt.u32.u64 %0, t; }" : "=r"(a) : "l"(p));
    return a;
}
__device__ __forceinline__ void ldm4(uint32_t& r0, uint32_t& r1, uint32_t& r2, uint32_t& r3,
                                     uint32_t addr) {
    asm volatile("ldmatrix.sync.aligned.m8n8.x4.shared.b16 {%0,%1,%2,%3}, [%4];"
                 : "=r"(r0), "=r"(r1), "=r"(r2), "=r"(r3) : "r"(addr));
}
__device__ __forceinline__ void ldm4t(uint32_t& r0, uint32_t& r1, uint32_t& r2, uint32_t& r3,
                                      uint32_t addr) {
    asm volatile("ldmatrix.sync.aligned.m8n8.x4.trans.shared.b16 {%0,%1,%2,%3}, [%4];"
                 : "=r"(r0), "=r"(r1), "=r"(r2), "=r"(r3) : "r"(addr));
}
__device__ __forceinline__ void mma16816(float* d, uint32_t a0, uint32_t a1, uint32_t a2,
                                         uint32_t a3, uint32_t b0, uint32_t b1) {
    asm volatile("mma.sync.aligned.m16n8k16.row.col.f32.bf16.bf16.f32 "
                 "{%0,%1,%2,%3}, {%4,%5,%6,%7}, {%8,%9}, {%0,%1,%2,%3};"
                 : "+f"(d[0]), "+f"(d[1]), "+f"(d[2]), "+f"(d[3])
                 : "r"(a0), "r"(a1), "r"(a2), "r"(a3), "r"(b0), "r"(b1));
}

// ---------------- zero counts ----------------
__global__ void k_zero() {
    int i = blockIdx.x * blockDim.x + threadIdx.x;
    if (i < C) g_cnt[i] = 0;
}

// ---------------- segment sum as GEMM: partial[c][d] = OneHot^T @ S ----------------
// 512 CTAs: kc = b>>1 (1024 rows), h = b&1 (dim half). 16 tiles of 64 rows.
#define KCHUNK   1024
#define NTILES   16
#define TROWS    64
#define OFF_OH   32768
#define OFF_LAB  40960
#define OFF_CNT  41472
#define SEG_SMEM (OFF_CNT + 256)

__global__ void __launch_bounds__(256, 2) k_seg(const float* __restrict__ S,
                                                const int* __restrict__ L) {
    uint32_t sb = smem_u32(smem_raw);
    int* labs = (int*)(smem_raw + OFF_LAB);
    int* cnts = (int*)(smem_raw + OFF_CNT);
    const int tid = threadIdx.x;
    const int wid = tid >> 5;
    const int lid = tid & 31;
    const int kc  = blockIdx.x >> 1;
    const int h   = blockIdx.x & 1;
    const size_t rowbase = (size_t)kc * KCHUNK;
    const float4* Sp = (const float4*)S;

    if (tid < C) cnts[tid] = 0;
#pragma unroll
    for (int i = 0; i < 2; i++)
        ((uint4*)(smem_raw + OFF_OH))[tid + i * 256] = make_uint4(0, 0, 0, 0);
    __syncthreads();
    if (h == 0) {
#pragma unroll
        for (int j = 0; j < 4; j++)
            atomicAdd(&cnts[__ldg(L + rowbase + j * 256 + tid)], 1);
    }

    float acc[4][2][4];
#pragma unroll
    for (int mt = 0; mt < 4; mt++)
#pragma unroll
        for (int nt = 0; nt < 2; nt++)
#pragma unroll
            for (int j = 0; j < 4; j++) acc[mt][nt][j] = 0.0f;

    float4 pf[8];
    auto ldg_tile = [&](int t) {
#pragma unroll
        for (int it = 0; it < 8; it++) {
            int f = it * 256 + tid;
            int trow = f >> 5, col4 = f & 31;
            pf[it] = __ldg(Sp + (rowbase + t * TROWS + trow) * 64 + h * 32 + col4);
        }
    };
    auto sts_tile = [&](int buf) {
#pragma unroll
        for (int it = 0; it < 8; it++) {
            int f = it * 256 + tid;
            int trow = f >> 5, col4 = f & 31;
            __nv_bfloat162 p0 = __floats2bfloat162_rn(pf[it].x, pf[it].y);
            __nv_bfloat162 p1 = __floats2bfloat162_rn(pf[it].z, pf[it].w);
            uint2 u = { *(uint32_t*)&p0, *(uint32_t*)&p1 };
            uint32_t addr = buf * 16384 + trow * 256 +
                            ((((col4 >> 1) ^ (trow & 7))) << 4) + ((col4 & 1) << 3);
            *(uint2*)(smem_raw + addr) = u;
        }
    };
    auto ldg_labels = [&](int t, int buf) {
        if (tid < TROWS) labs[buf * 64 + tid] = __ldg(L + rowbase + t * TROWS + tid);
    };

    uint32_t oldaddr = 0xFFFFFFFFu;
    const unsigned short one_bf = 0x3F80u;
    auto scatter = [&](int buf) {
        if (tid < TROWS) {
            int lab = labs[buf * 64 + tid];
            uint32_t addr = OFF_OH + lab * 128 + ((((tid >> 3) ^ (lab & 7))) << 4) + (tid & 7) * 2;
            if (oldaddr != 0xFFFFFFFFu) *(unsigned short*)(smem_raw + oldaddr) = 0;
            *(unsigned short*)(smem_raw + addr) = one_bf;
            oldaddr = addr;
        }
    };

    const int am    = lid >> 3;
    const int mrow0 = (am & 1) * 8 + (lid & 7);
    const int agsel = am >> 1;
    auto mma_tile = [&](int buf) {
#pragma unroll
        for (int ks = 0; ks < 4; ks++) {
            uint32_t a[4][4];
#pragma unroll
            for (int mt = 0; mt < 4; mt++) {
                int m = mt * 16 + mrow0;
                uint32_t g = ks * 2 + agsel;
                ldm4(a[mt][0], a[mt][1], a[mt][2], a[mt][3],
                     sb + OFF_OH + m * 128 + (((g ^ (m & 7))) << 4));
            }
            uint32_t f0, f1, f2, f3;
            {
                int trow = ks * 16 + (am & 1) * 8 + (lid & 7);
                uint32_t g = 2 * wid + (am >> 1);
                ldm4t(f0, f1, f2, f3,
                      sb + buf * 16384 + trow * 256 + (((g ^ (trow & 7))) << 4));
            }
#pragma unroll
            for (int mt = 0; mt < 4; mt++) {
                mma16816(acc[mt][0], a[mt][0], a[mt][1], a[mt][2], a[mt][3], f0, f1);
                mma16816(acc[mt][1], a[mt][0], a[mt][1], a[mt][2], a[mt][3], f2, f3);
            }
        }
    };

    ldg_tile(0);
    ldg_labels(0, 0);
    sts_tile(0);
    __syncthreads();

    for (int t = 0; t < NTILES; t++) {
        scatter(t & 1);
        if (t + 1 < NTILES) { ldg_tile(t + 1); ldg_labels(t + 1, (t + 1) & 1); }
        __syncthreads();
        mma_tile(t & 1);
        if (t + 1 < NTILES) sts_tile((t + 1) & 1);
        __syncthreads();
    }

    float* part = g_part + (size_t)blockIdx.x * 8192;
#pragma unroll
    for (int mt = 0; mt < 4; mt++)
#pragma unroll
        for (int nt = 0; nt < 2; nt++) {
            int r0 = 16 * mt + (lid >> 2);
            int dd = 16 * wid + 8 * nt + 2 * (lid & 3);
            float2 lo2 = { acc[mt][nt][0], acc[mt][nt][1] };
            float2 hi2 = { acc[mt][nt][2], acc[mt][nt][3] };
            __stcs((float2*)(part + r0 * 128 + dd), lo2);
            __stcs((float2*)(part + (r0 + 8) * 128 + dd), hi2);
        }
    if (h == 0 && tid < C) atomicAdd(&g_cnt[tid], cnts[tid]);
}

// ---------------- stage-1 reduce: 512 partials -> 8 (parity-preserving) ----------------
__global__ void __launch_bounds__(256) k_red() {
    const int slice = blockIdx.x & 31;
    const int gg    = (blockIdx.x >> 5) & 3;
    const int h     = blockIdx.x >> 7;
    const int e     = slice * 256 + threadIdx.x;
    const float* src = g_part + (size_t)((gg * 64) * 2 + h) * 8192 + e;
    float s = 0.0f;
#pragma unroll 8
    for (int j = 0; j < 64; j++) s += __ldg(src + (size_t)j * 16384);
    g_red[(h * 4 + gg) * 8192 + e] = s;
}

// ---------------- finalize: reduce 8, normalize, bf16 swizzle + K-PERMUTE ----------------
// Physical slot within each 16-group: for logical l = 4q + 2h' + e  ->  p = 8h' + 2q + e.
// This makes B fragment slot s line up with A's float4-loaded gmem col (see k_query).
__global__ void __launch_bounds__(256) k_fin2() {
    __shared__ float red[256];
    const int c = blockIdx.x, t = threadIdx.x;
    const int h = t >> 7, dl = t & 127;
    const float* src = g_red + (size_t)h * 4 * 8192 + c * 128 + dl;
    float s = 0.0f;
#pragma unroll
    for (int g = 0; g < 4; g++) s += __ldg(src + (size_t)g * 8192);

    float inv_d = 1.0f / fmaxf((float)g_cnt[c], 1.0f);
    float p = s * inv_d;
    red[t] = p * p;
    __syncthreads();
    for (int st = 128; st > 0; st >>= 1) {
        if (t < st) red[t] += red[t + st];
        __syncthreads();
    }
    float inv = 1.0f / fmaxf(sqrtf(red[0]), 1e-8f);
    int tp = (t & 0xF0) | (((t >> 1) & 1) << 3) | (((t >> 2) & 3) << 1) | (t & 1);
    uint32_t byte = (uint32_t)(c * 512 + ((((tp >> 3) ^ (c & 7))) << 4) + (tp & 7) * 2);
    ((__nv_bfloat16*)g_Pbf4)[byte >> 1] = __float2bfloat16_rn(p * inv);
}

// fast exp on the FMA pipe
__device__ __forceinline__ float fexp(float x) {
    float y = x * 1.442695041f;
    float r = y + 12582912.0f;
    int n = __float_as_int(r) - 0x4B400000;
    float f = y - (r - 12582912.0f);
    float p = 1.3333558e-3f;
    p = fmaf(p, f, 9.6181291e-3f);
    p = fmaf(p, f, 5.5504109e-2f);
    p = fmaf(p, f, 2.4022651e-1f);
    p = fmaf(p, f, 6.9314718e-1f);
    p = fmaf(p, f, 1.0f);
    return __int_as_float(__float_as_int(p) + (n << 23));
}

// ---------------- query kernel v3: float4 A loads (k-permuted), 2-deep prefetch ----------------
#define SMEM_QRY 32768

__global__ void __launch_bounds__(256, 3) k_query(const float* __restrict__ Q,
                                                  float* __restrict__ out) {
    uint32_t sb = smem_u32(smem_raw);
    const int tid = threadIdx.x;
    const int wid = tid >> 5;
    const int lid = tid & 31;
    const int qbase = blockIdx.x * MT;

#pragma unroll
    for (int it = 0; it < 8; it++)
        ((uint4*)smem_raw)[tid + it * 256] = g_Pbf4[tid + it * 256];
    __syncthreads();

    const int rA = wid * 16 + (lid >> 2);
    // lane owns gmem cols s*16 + 4q .. +3 (per kstep) of rows rA and rA+8
    const float* qA = Q + (size_t)(qbase + rA) * D + 4 * (lid & 3);
    const float* qB = qA + 8 * D;

    const int brow0 = ((lid >> 3) >> 1) * 8 + (lid & 7);
    const int bgsel = (lid >> 3) & 1;

    float dacc[8][4];
#pragma unroll
    for (int nt = 0; nt < 8; nt++)
#pragma unroll
        for (int j = 0; j < 4; j++) dacc[nt][j] = 0.0f;

    float ssq0 = 0.0f, ssq1 = 0.0f;

    float4 bufA[2], bufB[2];
    bufA[0] = __ldg((const float4*)(qA));
    bufB[0] = __ldg((const float4*)(qB));
    bufA[1] = __ldg((const float4*)(qA + 16));
    bufB[1] = __ldg((const float4*)(qB + 16));

#pragma unroll
    for (int s = 0; s < 16; s++) {
        float4 vA = bufA[s & 1];
        float4 vB = bufB[s & 1];
        if (s < 14) {
            bufA[s & 1] = __ldg((const float4*)(qA + (s + 2) * 16));
            bufB[s & 1] = __ldg((const float4*)(qB + (s + 2) * 16));
        }
        ssq0 = fmaf(vA.x, vA.x, ssq0); ssq0 = fmaf(vA.y, vA.y, ssq0);
        ssq0 = fmaf(vA.z, vA.z, ssq0); ssq0 = fmaf(vA.w, vA.w, ssq0);
        ssq1 = fmaf(vB.x, vB.x, ssq1); ssq1 = fmaf(vB.y, vB.y, ssq1);
        ssq1 = fmaf(vB.z, vB.z, ssq1); ssq1 = fmaf(vB.w, vB.w, ssq1);

        __nv_bfloat162 ba0 = __floats2bfloat162_rn(vA.x, vA.y);
        __nv_bfloat162 ba2 = __floats2bfloat162_rn(vA.z, vA.w);
        __nv_bfloat162 ba1 = __floats2bfloat162_rn(vB.x, vB.y);
        __nv_bfloat162 ba3 = __floats2bfloat162_rn(vB.z, vB.w);
        uint32_t a0 = *(uint32_t*)&ba0, a1 = *(uint32_t*)&ba1;
        uint32_t a2 = *(uint32_t*)&ba2, a3 = *(uint32_t*)&ba3;

        uint32_t bfr[16];
#pragma unroll
        for (int pp = 0; pp < 4; pp++) {
            int row = pp * 16 + brow0;
            uint32_t g = 2 * s + bgsel;
            ldm4(bfr[pp * 4], bfr[pp * 4 + 1], bfr[pp * 4 + 2], bfr[pp * 4 + 3],
                 sb + row * 512 + (((g ^ (row & 7))) << 4));
        }
#pragma unroll
        for (int nt = 0; nt < 8; nt++)
            mma16816(dacc[nt], a0, a1, a2, a3, bfr[nt * 2], bfr[nt * 2 + 1]);
    }

    ssq0 += __shfl_xor_sync(0xffffffffu, ssq0, 1);
    ssq0 += __shfl_xor_sync(0xffffffffu, ssq0, 2);
    ssq1 += __shfl_xor_sync(0xffffffffu, ssq1, 1);
    ssq1 += __shfl_xor_sync(0xffffffffu, ssq1, 2);

    float dA[16], dB[16];
#pragma unroll
    for (int nt = 0; nt < 8; nt++) {
        dA[nt * 2] = dacc[nt][0]; dA[nt * 2 + 1] = dacc[nt][1];
        dB[nt * 2] = dacc[nt][2]; dB[nt * 2 + 1] = dacc[nt][3];
    }
    float invA = 1.0f / fmaxf(sqrtf(ssq0), 1e-8f);
    float invB = 1.0f / fmaxf(sqrtf(ssq1), 1e-8f);

    float mA = -3.4e38f, mB = -3.4e38f;
#pragma unroll
    for (int j = 0; j < 16; j++) {
        dA[j] *= invA; mA = fmaxf(mA, dA[j]);
        dB[j] *= invB; mB = fmaxf(mB, dB[j]);
    }
#pragma unroll
    for (int w = 1; w < 4; w <<= 1) {
        mA = fmaxf(mA, __shfl_xor_sync(0xffffffffu, mA, w));
        mB = fmaxf(mB, __shfl_xor_sync(0xffffffffu, mB, w));
    }
    float sA = 0.0f, sB = 0.0f;
#pragma unroll
    for (int j = 0; j < 16; j++) {
        sA += fexp(dA[j] - mA);
        sB += fexp(dB[j] - mB);
    }
#pragma unroll
    for (int w = 1; w < 4; w <<= 1) {
        sA += __shfl_xor_sync(0xffffffffu, sA, w);
        sB += __shfl_xor_sync(0xffffffffu, sB, w);
    }
    float lseA = mA + logf(sA);
    float lseB = mB + logf(sB);

    float* oA = out + (size_t)(qbase + rA) * C + (lid & 3) * 2;
    float* oB = oA + 8 * C;
#pragma unroll
    for (int nt = 0; nt < 8; nt++) {
        float2 a = { dA[nt * 2] - lseA, dA[nt * 2 + 1] - lseA };
        float2 b = { dB[nt * 2] - lseB, dB[nt * 2 + 1] - lseB };
        *(float2*)(oA + nt * 8) = a;
        *(float2*)(oB + nt * 8) = b;
    }
}

extern "C" void kernel_launch(void* const* d_in, const int* in_sizes, int n_in,
                              void* d_out, int out_size) {
    const float* support = (const float*)d_in[0];
    const int*   labels  = (const int*)d_in[1];
    const float* query   = (const float*)d_in[2];
    float*       out     = (float*)d_out;

    cudaFuncSetAttribute(k_seg,   cudaFuncAttributeMaxDynamicSharedMemorySize, SEG_SMEM);
    cudaFuncSetAttribute(k_query, cudaFuncAttributeMaxDynamicSharedMemorySize, SMEM_QRY);

    k_zero<<<1, 256>>>();
    k_seg<<<512, 256, SEG_SMEM>>>(support, labels);
    k_red<<<256, 256>>>();
    k_fin2<<<C, 256>>>();
    k_query<<<NQ / MT, 256, SMEM_QRY>>>(query, out);
}

// round 12
// speedup vs baseline: 2.1699x; 1.0063x over previous
#include <cuda_runtime.h>
#include <cuda_bf16.h>
#include <math.h>
#include <stdint.h>

#define NQ 131072
#define NS 262144
#define D  256
#define C  64
#define MT 128

// ---------------- device scratch ----------------
__device__ int   g_cntp[256 * 64];          // per-kc histograms (h==0 CTAs)
__device__ float g_cntF[64];                // reduced counts (k_red CTA 0)
__device__ uint4 g_Pbf4[2048];              // 32KB: prototypes bf16, swizzled+k-permuted, /p_norm
__device__ float g_part[512 * 8192];        // 16MB: per-CTA partial [64][128]
__device__ float g_red[8 * 8192];           // 256KB: stage-1 reduced partials

extern __shared__ char smem_raw[];

__device__ __forceinline__ uint32_t smem_u32(const void* p) {
    uint32_t a;
    asm("{ .reg .u64 t; cvta.to.shared.u64 t, %1; cvt.u32.u64 %0, t; }" : "=r"(a) : "l"(p));
    return a;
}
__device__ __forceinline__ void ldm4(uint32_t& r0, uint32_t& r1, uint32_t& r2, uint32_t& r3,
                                     uint32_t addr) {
    asm volatile("ldmatrix.sync.aligned.m8n8.x4.shared.b16 {%0,%1,%2,%3}, [%4];"
                 : "=r"(r0), "=r"(r1), "=r"(r2), "=r"(r3) : "r"(addr));
}
__device__ __forceinline__ void ldm4t(uint32_t& r0, uint32_t& r1, uint32_t& r2, uint32_t& r3,
                                      uint32_t addr) {
    asm volatile("ldmatrix.sync.aligned.m8n8.x4.trans.shared.b16 {%0,%1,%2,%3}, [%4];"
                 : "=r"(r0), "=r"(r1), "=r"(r2), "=r"(r3) : "r"(addr));
}
__device__ __forceinline__ void mma16816(float* d, uint32_t a0, uint32_t a1, uint32_t a2,
                                         uint32_t a3, uint32_t b0, uint32_t b1) {
    asm volatile("mma.sync.aligned.m16n8k16.row.col.f32.bf16.bf16.f32 "
                 "{%0,%1,%2,%3}, {%4,%5,%6,%7}, {%8,%9}, {%0,%1,%2,%3};"
                 : "+f"(d[0]), "+f"(d[1]), "+f"(d[2]), "+f"(d[3])
                 : "r"(a0), "r"(a1), "r"(a2), "r"(a3), "r"(b0), "r"(b1));
}

// ---------------- segment sum as GEMM: partial[c][d] = OneHot^T @ S ----------------
// 512 CTAs: kc = b>>1 (1024 rows), h = b&1 (dim half). 16 tiles of 64 rows.
// Single-sync pipeline: double-buffered onehot, register-resident labels.
// smem: S double buf 2x16KB @0, onehot x2 8KB @32768/@40960, cnt @49152
#define KCHUNK   1024
#define NTILES   16
#define TROWS    64
#define OFF_OH   32768
#define OFF_CNT  49152
#define SEG_SMEM (OFF_CNT + 256)

__global__ void __launch_bounds__(256, 2) k_seg(const float* __restrict__ S,
                                                const int* __restrict__ L) {
    uint32_t sb = smem_u32(smem_raw);
    int* cnts = (int*)(smem_raw + OFF_CNT);
    const int tid = threadIdx.x;
    const int wid = tid >> 5;
    const int lid = tid & 31;
    const int kc  = blockIdx.x >> 1;
    const int h   = blockIdx.x & 1;
    const size_t rowbase = (size_t)kc * KCHUNK;
    const float4* Sp = (const float4*)S;

    if (tid < C) cnts[tid] = 0;
    // zero both onehot buffers (16KB)
#pragma unroll
    for (int i = 0; i < 4; i++)
        ((uint4*)(smem_raw + OFF_OH))[tid + i * 256] = make_uint4(0, 0, 0, 0);
    __syncthreads();

    float acc[4][2][4];
#pragma unroll
    for (int mt = 0; mt < 4; mt++)
#pragma unroll
        for (int nt = 0; nt < 2; nt++)
#pragma unroll
            for (int j = 0; j < 4; j++) acc[mt][nt][j] = 0.0f;

    float4 pf[8];
    auto ldg_tile = [&](int t) {
#pragma unroll
        for (int it = 0; it < 8; it++) {
            int f = it * 256 + tid;
            int trow = f >> 5, col4 = f & 31;
            pf[it] = __ldg(Sp + (rowbase + t * TROWS + trow) * 64 + h * 32 + col4);
        }
    };
    auto sts_tile = [&](int buf) {
#pragma unroll
        for (int it = 0; it < 8; it++) {
            int f = it * 256 + tid;
            int trow = f >> 5, col4 = f & 31;
            __nv_bfloat162 p0 = __floats2bfloat162_rn(pf[it].x, pf[it].y);
            __nv_bfloat162 p1 = __floats2bfloat162_rn(pf[it].z, pf[it].w);
            uint2 u = { *(uint32_t*)&p0, *(uint32_t*)&p1 };
            uint32_t addr = buf * 16384 + trow * 256 +
                            ((((col4 >> 1) ^ (trow & 7))) << 4) + ((col4 & 1) << 3);
            *(uint2*)(smem_raw + addr) = u;
        }
    };

    // register-resident label prefetch (thread tid<64 owns tile-row tid)
    const unsigned short one_bf = 0x3F80u;
    uint32_t oldA[2] = { 0xFFFFFFFFu, 0xFFFFFFFFu };
    int labp[2] = { 0, 0 };

    // prologue: labels for tiles 0..2, scatter tile 0, stage tile 0
    int lab0 = 0;
    if (tid < TROWS) {
        lab0    = __ldg(L + rowbase + tid);
        labp[1] = __ldg(L + rowbase + 64 + tid);     // tile 1
        labp[0] = __ldg(L + rowbase + 128 + tid);    // tile 2
    }
    ldg_tile(0);
    if (tid < TROWS) {
        uint32_t addr = OFF_OH + lab0 * 128 + ((((tid >> 3) ^ (lab0 & 7))) << 4) + (tid & 7) * 2;
        *(unsigned short*)(smem_raw + addr) = one_bf;
        oldA[0] = addr;
    }
    sts_tile(0);
    __syncthreads();

    if (h == 0) {
#pragma unroll
        for (int j = 0; j < 4; j++)
            atomicAdd(&cnts[__ldg(L + rowbase + j * 256 + tid)], 1);
    }

    const int am    = lid >> 3;
    const int mrow0 = (am & 1) * 8 + (lid & 7);
    const int agsel = am >> 1;
    auto mma_tile = [&](int buf) {
        uint32_t ohb = OFF_OH + buf * 8192;
#pragma unroll
        for (int ks = 0; ks < 4; ks++) {
            uint32_t a[4][4];
#pragma unroll
            for (int mt = 0; mt < 4; mt++) {
                int m = mt * 16 + mrow0;
                uint32_t g = ks * 2 + agsel;
                ldm4(a[mt][0], a[mt][1], a[mt][2], a[mt][3],
                     sb + ohb + m * 128 + (((g ^ (m & 7))) << 4));
            }
            uint32_t f0, f1, f2, f3;
            {
                int trow = ks * 16 + (am & 1) * 8 + (lid & 7);
                uint32_t g = 2 * wid + (am >> 1);
                ldm4t(f0, f1, f2, f3,
                      sb + buf * 16384 + trow * 256 + (((g ^ (trow & 7))) << 4));
            }
#pragma unroll
            for (int mt = 0; mt < 4; mt++) {
                mma16816(acc[mt][0], a[mt][0], a[mt][1], a[mt][2], a[mt][3], f0, f1);
                mma16816(acc[mt][1], a[mt][0], a[mt][1], a[mt][2], a[mt][3], f2, f3);
            }
        }
    };

    for (int t = 0; t < NTILES; t++) {
        int b = t & 1;
        if (t + 1 < NTILES) ldg_tile(t + 1);
        mma_tile(b);
        if (t + 1 < NTILES && tid < TROWS) {
            int nb = 1 - b;
            int lab = labp[nb];
            uint32_t addr = OFF_OH + nb * 8192 + lab * 128 +
                            ((((tid >> 3) ^ (lab & 7))) << 4) + (tid & 7) * 2;
            if (oldA[nb] != 0xFFFFFFFFu) *(unsigned short*)(smem_raw + oldA[nb]) = 0;
            *(unsigned short*)(smem_raw + addr) = one_bf;
            oldA[nb] = addr;
            if (t + 3 < NTILES) labp[nb] = __ldg(L + rowbase + (t + 3) * 64 + tid);
        }
        if (t + 1 < NTILES) sts_tile(1 - b);
        __syncthreads();
    }

    float* part = g_part + (size_t)blockIdx.x * 8192;
#pragma unroll
    for (int mt = 0; mt < 4; mt++)
#pragma unroll
        for (int nt = 0; nt < 2; nt++) {
            int r0 = 16 * mt + (lid >> 2);
            int dd = 16 * wid + 8 * nt + 2 * (lid & 3);
            float2 lo2 = { acc[mt][nt][0], acc[mt][nt][1] };
            float2 hi2 = { acc[mt][nt][2], acc[mt][nt][3] };
            __stcs((float2*)(part + r0 * 128 + dd), lo2);
            __stcs((float2*)(part + (r0 + 8) * 128 + dd), hi2);
        }
    if (h == 0 && tid < C) g_cntp[kc * 64 + tid] = cnts[tid];
}

// ---------------- stage-1 reduce: 512 partials -> 8; CTA 0 also reduces counts ----------------
__global__ void __launch_bounds__(256) k_red() {
    const int slice = blockIdx.x & 31;
    const int gg    = (blockIdx.x >> 5) & 3;
    const int h     = blockIdx.x >> 7;
    const int e     = slice * 256 + threadIdx.x;
    const float* src = g_part + (size_t)((gg * 64) * 2 + h) * 8192 + e;
    float s = 0.0f;
#pragma unroll 8
    for (int j = 0; j < 64; j++) s += __ldg(src + (size_t)j * 16384);
    g_red[(h * 4 + gg) * 8192 + e] = s;

    if (blockIdx.x == 0) {
        int c = threadIdx.x >> 2, g4 = threadIdx.x & 3;
        float cs = 0.0f;
#pragma unroll 8
        for (int j = 0; j < 64; j++) cs += (float)__ldg(&g_cntp[(g4 * 64 + j) * 64 + c]);
        cs += __shfl_xor_sync(0xffffffffu, cs, 1);
        cs += __shfl_xor_sync(0xffffffffu, cs, 2);
        if ((threadIdx.x & 3) == 0) g_cntF[c] = cs;
    }
}

// ---------------- finalize: reduce 8, normalize, bf16 swizzle + K-PERMUTE ----------------
__global__ void __launch_bounds__(256) k_fin2() {
    __shared__ float red[256];
    const int c = blockIdx.x, t = threadIdx.x;
    const int h = t >> 7, dl = t & 127;
    const float* src = g_red + (size_t)h * 4 * 8192 + c * 128 + dl;
    float s = 0.0f;
#pragma unroll
    for (int g = 0; g < 4; g++) s += __ldg(src + (size_t)g * 8192);

    float inv_d = 1.0f / fmaxf(__ldg(&g_cntF[c]), 1.0f);
    float p = s * inv_d;
    red[t] = p * p;
    __syncthreads();
    for (int st = 128; st > 0; st >>= 1) {
        if (t < st) red[t] += red[t + st];
        __syncthreads();
    }
    float inv = 1.0f / fmaxf(sqrtf(red[0]), 1e-8f);
    int tp = (t & 0xF0) | (((t >> 1) & 1) << 3) | (((t >> 2) & 3) << 1) | (t & 1);
    uint32_t byte = (uint32_t)(c * 512 + ((((tp >> 3) ^ (c & 7))) << 4) + (tp & 7) * 2);
    ((__nv_bfloat16*)g_Pbf4)[byte >> 1] = __float2bfloat16_rn(p * inv);
}

// fast exp on the FMA pipe
__device__ __forceinline__ float fexp(float x) {
    float y = x * 1.442695041f;
    float r = y + 12582912.0f;
    int n = __float_as_int(r) - 0x4B400000;
    float f = y - (r - 12582912.0f);
    float p = 1.3333558e-3f;
    p = fmaf(p, f, 9.6181291e-3f);
    p = fmaf(p, f, 5.5504109e-2f);
    p = fmaf(p, f, 2.4022651e-1f);
    p = fmaf(p, f, 6.9314718e-1f);
    p = fmaf(p, f, 1.0f);
    return __int_as_float(__float_as_int(p) + (n << 23));
}

// ---------------- query kernel: float4 A loads (k-permuted), no-max softmax ----------------
#define SMEM_QRY 32768

__global__ void __launch_bounds__(256, 3) k_query(const float* __restrict__ Q,
                                                  float* __restrict__ out) {
    uint32_t sb = smem_u32(smem_raw);
    const int tid = threadIdx.x;
    const int wid = tid >> 5;
    const int lid = tid & 31;
    const int qbase = blockIdx.x * MT;

#pragma unroll
    for (int it = 0; it < 8; it++)
        ((uint4*)smem_raw)[tid + it * 256] = g_Pbf4[tid + it * 256];
    __syncthreads();

    const int rA = wid * 16 + (lid >> 2);
    const float* qA = Q + (size_t)(qbase + rA) * D + 4 * (lid & 3);
    const float* qB = qA + 8 * D;

    const int brow0 = ((lid >> 3) >> 1) * 8 + (lid & 7);
    const int bgsel = (lid >> 3) & 1;

    float dacc[8][4];
#pragma unroll
    for (int nt = 0; nt < 8; nt++)
#pragma unroll
        for (int j = 0; j < 4; j++) dacc[nt][j] = 0.0f;

    float ssq0 = 0.0f, ssq1 = 0.0f;

    float4 bufA[2], bufB[2];
    bufA[0] = __ldg((const float4*)(qA));
    bufB[0] = __ldg((const float4*)(qB));
    bufA[1] = __ldg((const float4*)(qA + 16));
    bufB[1] = __ldg((const float4*)(qB + 16));

#pragma unroll
    for (int s = 0; s < 16; s++) {
        float4 vA = bufA[s & 1];
        float4 vB = bufB[s & 1];
        if (s < 14) {
            bufA[s & 1] = __ldg((const float4*)(qA + (s + 2) * 16));
            bufB[s & 1] = __ldg((const float4*)(qB + (s + 2) * 16));
        }
        ssq0 = fmaf(vA.x, vA.x, ssq0); ssq0 = fmaf(vA.y, vA.y, ssq0);
        ssq0 = fmaf(vA.z, vA.z, ssq0); ssq0 = fmaf(vA.w, vA.w, ssq0);
        ssq1 = fmaf(vB.x, vB.x, ssq1); ssq1 = fmaf(vB.y, vB.y, ssq1);
        ssq1 = fmaf(vB.z, vB.z, ssq1); ssq1 = fmaf(vB.w, vB.w, ssq1);

        __nv_bfloat162 ba0 = __floats2bfloat162_rn(vA.x, vA.y);
        __nv_bfloat162 ba2 = __floats2bfloat162_rn(vA.z, vA.w);
        __nv_bfloat162 ba1 = __floats2bfloat162_rn(vB.x, vB.y);
        __nv_bfloat162 ba3 = __floats2bfloat162_rn(vB.z, vB.w);
        uint32_t a0 = *(uint32_t*)&ba0, a1 = *(uint32_t*)&ba1;
        uint32_t a2 = *(uint32_t*)&ba2, a3 = *(uint32_t*)&ba3;

        uint32_t bfr[16];
#pragma unroll
        for (int pp = 0; pp < 4; pp++) {
            int row = pp * 16 + brow0;
            uint32_t g = 2 * s + bgsel;
            ldm4(bfr[pp * 4], bfr[pp * 4 + 1], bfr[pp * 4 + 2], bfr[pp * 4 + 3],
                 sb + row * 512 + (((g ^ (row & 7))) << 4));
        }
#pragma unroll
        for (int nt = 0; nt < 8; nt++)
            mma16816(dacc[nt], a0, a1, a2, a3, bfr[nt * 2], bfr[nt * 2 + 1]);
    }

    ssq0 += __shfl_xor_sync(0xffffffffu, ssq0, 1);
    ssq0 += __shfl_xor_sync(0xffffffffu, ssq0, 2);
    ssq1 += __shfl_xor_sync(0xffffffffu, ssq1, 1);
    ssq1 += __shfl_xor_sync(0xffffffffu, ssq1, 2);

    float dA[16], dB[16];
#pragma unroll
    for (int nt = 0; nt < 8; nt++) {
        dA[nt * 2] = dacc[nt][0]; dA[nt * 2 + 1] = dacc[nt][1];
        dB[nt * 2] = dacc[nt][2]; dB[nt * 2 + 1] = dacc[nt][3];
    }
    float invA = 1.0f / fmaxf(sqrtf(ssq0), 1e-8f);
    float invB = 1.0f / fmaxf(sqrtf(ssq1), 1e-8f);

    // sims bounded in [-1,1] -> no max-subtraction needed
    float sA = 0.0f, sB = 0.0f;
#pragma unroll
    for (int j = 0; j < 16; j++) {
        dA[j] *= invA; sA += fexp(dA[j]);
        dB[j] *= invB; sB += fexp(dB[j]);
    }
#pragma unroll
    for (int w = 1; w < 4; w <<= 1) {
        sA += __shfl_xor_sync(0xffffffffu, sA, w);
        sB += __shfl_xor_sync(0xffffffffu, sB, w);
    }
    float lseA = logf(sA);
    float lseB = logf(sB);

    float* oA = out + (size_t)(qbase + rA) * C + (lid & 3) * 2;
    float* oB = oA + 8 * C;
#pragma unroll
    for (int nt = 0; nt < 8; nt++) {
        float2 a = { dA[nt * 2] - lseA, dA[nt * 2 + 1] - lseA };
        float2 b = { dB[nt * 2] - lseB, dB[nt * 2 + 1] - lseB };
        *(float2*)(oA + nt * 8) = a;
        *(float2*)(oB + nt * 8) = b;
    }
}

extern "C" void kernel_launch(void* const* d_in, const int* in_sizes, int n_in,
                              void* d_out, int out_size) {
    const float* support = (const float*)d_in[0];
    const int*   labels  = (const int*)d_in[1];
    const float* query   = (const float*)d_in[2];
    float*       out     = (float*)d_out;

    cudaFuncSetAttribute(k_seg,   cudaFuncAttributeMaxDynamicSharedMemorySize, SEG_SMEM);
    cudaFuncSetAttribute(k_query, cudaFuncAttributeMaxDynamicSharedMemorySize, SMEM_QRY);

    k_seg<<<512, 256, SEG_SMEM>>>(support, labels);
    k_red<<<256, 256>>>();
    k_fin2<<<C, 256>>>();
    k_query<<<NQ / MT, 256, SMEM_QRY>>>(query, out);
}